// round 6
// baseline (speedup 1.0000x reference)
#include <cuda_runtime.h>
#include <math.h>
#include <stdint.h>

// Problem dims
#define BCH 4
#define CCH 256
#define HWT 4096          // H*W = 64*64
#define NTOK 16384        // B*HW

// Token order inside each batch is PERMUTED: p = w*64 + h. Causal mask becomes
// block-lower-triangular at 64-token granularity, diagonal fully allowed.

// ---------------- scratch ------------------------------------------------------
__device__ float g_hn_hi[(size_t)NTOK * CCH];
__device__ float g_hn_lo[(size_t)NTOK * CCH];
__device__ float g_q_hi [(size_t)NTOK * CCH];
__device__ float g_q_lo [(size_t)NTOK * CCH];
__device__ float g_k_hi [(size_t)NTOK * CCH];
__device__ float g_k_lo [(size_t)NTOK * CCH];
__device__ float g_vt   [(size_t)NTOK * CCH];   // [b][c][p], tf32-rounded
__device__ float g_h_hi [(size_t)NTOK * CCH];
__device__ float g_h_lo [(size_t)NTOK * CCH];
__device__ float g_wt_hi[4 * CCH * CCH];        // transposed+split weights
__device__ float g_wt_lo[4 * CCH * CCH];
__device__ float g_s    [(size_t)BCH * HWT * HWT];

// ---------------- helpers -----------------------------------------------------
__device__ __forceinline__ uint32_t smem_u32(const void* p) {
    uint32_t a;
    asm("{ .reg .u64 t; cvta.to.shared.u64 t, %1; cvt.u32.u64 %0, t; }"
        : "=r"(a) : "l"(p));
    return a;
}
__device__ __forceinline__ float rna_tf32f(float x) {
    uint32_t u;
    asm("cvt.rna.tf32.f32 %0, %1;" : "=r"(u) : "f"(x));
    return __uint_as_float(u);
}
__device__ __forceinline__ void cpa16(uint32_t dst, const void* src) {
    asm volatile("cp.async.cg.shared.global [%0], [%1], 16;"
                 :: "r"(dst), "l"(src));
}
__device__ __forceinline__ void cpa_commit() {
    asm volatile("cp.async.commit_group;" ::: "memory");
}
__device__ __forceinline__ void cpa_wait1() {
    asm volatile("cp.async.wait_group 1;" ::: "memory");
}
__device__ __forceinline__ void mma8(float* c, const uint32_t* a, const uint32_t* b) {
    asm volatile("mma.sync.aligned.m16n8k8.row.col.f32.tf32.tf32.f32 "
        "{%0,%1,%2,%3}, {%4,%5,%6,%7}, {%8,%9}, {%0,%1,%2,%3};"
        : "+f"(c[0]), "+f"(c[1]), "+f"(c[2]), "+f"(c[3])
        : "r"(a[0]), "r"(a[1]), "r"(a[2]), "r"(a[3]), "r"(b[0]), "r"(b[1]));
}

// ---------------- GroupNorm -> permuted hn (hi/lo split) ----------------------
__global__ __launch_bounds__(256) void groupnorm_kernel(
    const float* __restrict__ x,
    const float* __restrict__ gnw,
    const float* __restrict__ gnb)
{
    __shared__ float tile[CCH][33];
    __shared__ float sw[CCH];
    __shared__ float sb[CCH];
    int tid = threadIdx.x;
    int b = blockIdx.x >> 7;
    int hwbase = (blockIdx.x & 127) << 5;
    int tx = tid & 31, ty = tid >> 5;

    const float* xb = x + (size_t)b * CCH * HWT;
    for (int c = ty; c < CCH; c += 8)
        tile[c][tx] = xb[(size_t)c * HWT + hwbase + tx];
    sw[tid] = gnw[tid];
    sb[tid] = gnb[tid];
    __syncthreads();

    int tok = tx;
    #pragma unroll
    for (int gi = 0; gi < 4; gi++) {
        int c0 = (ty + gi * 8) * 8;
        float s = 0.f, ss = 0.f;
        #pragma unroll
        for (int j = 0; j < 8; j++) {
            float v = tile[c0 + j][tok];
            s += v; ss += v * v;
        }
        float m   = s * 0.125f;
        float var = ss * 0.125f - m * m;
        float r   = rsqrtf(var + 1e-6f);
        #pragma unroll
        for (int j = 0; j < 8; j++) {
            int c = c0 + j;
            tile[c][tok] = (tile[c][tok] - m) * r * sw[c] + sb[c];
        }
    }
    __syncthreads();

    int h = hwbase >> 6;
    float* hh = g_hn_hi + ((size_t)b << 12) * CCH;
    float* hl = g_hn_lo + ((size_t)b << 12) * CCH;
    for (int it = 0; it < 32; it++) {
        int w = (hwbase + it) & 63;
        int p = (w << 6) | h;
        float v = tile[tid][it];
        float hi = rna_tf32f(v);
        hh[(size_t)p * CCH + tid] = hi;
        hl[(size_t)p * CCH + tid] = rna_tf32f(v - hi);
    }
}

// ---------------- weight prep: transpose + hi/lo split ------------------------
// w [K=256][N=256] row-major -> wt_hi/lo [N][K]
__global__ void wprep_kernel(const float* __restrict__ w,
                             float* __restrict__ whi,
                             float* __restrict__ wlo)
{
    __shared__ float t[32][33];
    int tx = threadIdx.x, ty = threadIdx.y;
    int bx = blockIdx.x * 32, by = blockIdx.y * 32;
    t[ty][tx] = w[(by + ty) * CCH + bx + tx];
    __syncthreads();
    float v = t[tx][ty];
    float hi = rna_tf32f(v);
    whi[(bx + ty) * CCH + by + tx] = hi;
    wlo[(bx + ty) * CCH + by + tx] = rna_tf32f(v - hi);
}

// ---------------- unified tensor-core NT GEMM ---------------------------------
// C[128x128] tiles; A [M][K] rm, B [N][K] rm. All operands pre-tf32-rounded.
// SPLIT3: 3xTF32 via A1/B1 lo arrays. TRI: scores (skip nt>mt).
// CAUSALK: PV (mt reversed, Ktile=128*(mt+1)).
// EPI 0: C=acc. 1: hi/lo split store (C,C2) of alpha*(acc+bias[n]).
//     2: C=rna(acc+bias[m])  (BIASM). 3: out scatter: x + acc + bias[n], unperm.
template <bool SPLIT3, bool TRI, bool CAUSALK, int EPI, bool BIASM>
__global__ __launch_bounds__(256) void mma_nt_kernel(
    const float* __restrict__ A0, const float* __restrict__ A1,
    const float* __restrict__ B0, const float* __restrict__ B1,
    float* __restrict__ C, float* __restrict__ C2,
    const float* __restrict__ bias, const float* __restrict__ xres,
    float alpha,
    int lda, int ldb, int ldc, int Kfull,
    long long strA, long long strB, long long strC)
{
    int nt = blockIdx.x, bz = blockIdx.z;
    int mt;
    if (TRI) {
        mt = blockIdx.y;
        if (nt > mt) return;
    } else if (CAUSALK) {
        mt = (int)gridDim.y - 1 - (int)blockIdx.y;
    } else {
        mt = blockIdx.y;
    }
    int Ktile = CAUSALK ? 128 * (mt + 1) : Kfull;

    extern __shared__ float sm[];
    uint32_t sbase = smem_u32(sm);

    int tid = threadIdx.x;
    int lane = tid & 31, wid = tid >> 5;
    int wm = (wid >> 2) * 64, wn = (wid & 3) * 32;
    int gid = lane >> 2, tg = lane & 3;

    const float* a0 = A0 + (long long)bz * strA + (long long)mt * 128 * lda;
    const float* b0 = B0 + (long long)bz * strB + (long long)nt * 128 * ldb;
    const float* a1 = SPLIT3 ? A1 + (long long)bz * strA + (long long)mt * 128 * lda : nullptr;
    const float* b1 = SPLIT3 ? B1 + (long long)bz * strB + (long long)nt * 128 * ldb : nullptr;

    int lrow = tid >> 1;
    int lcol0 = (tid & 1) * 16;

    float acc[4][4][4];
    #pragma unroll
    for (int mi = 0; mi < 4; mi++)
        #pragma unroll
        for (int ni = 0; ni < 4; ni++)
            #pragma unroll
            for (int e = 0; e < 4; e++) acc[mi][ni][e] = 0.f;

    // smem tile bases (bytes): tiles are 128x36 floats = 18432 B
    const uint32_t T = 18432u;
    const uint32_t AHI0 = 0, ALO0 = 2 * T;
    const uint32_t BHI0 = SPLIT3 ? 4 * T : 2 * T;
    const uint32_t BLO0 = 6 * T;

    uint32_t srow = sbase + (uint32_t)lrow * 144u + (uint32_t)lcol0 * 4u;
    const int NC = Ktile >> 5;

    // loader for one chunk into buffer p
    auto load_chunk = [&](int p, int koff) {
        uint32_t pb = (uint32_t)p * T;
        const float* ag0 = a0 + (long long)lrow * lda + koff + lcol0;
        const float* bg0 = b0 + (long long)lrow * ldb + koff + lcol0;
        #pragma unroll
        for (int i = 0; i < 4; i++) {
            cpa16(srow + AHI0 + pb + i * 16u, ag0 + i * 4);
            cpa16(srow + BHI0 + pb + i * 16u, bg0 + i * 4);
        }
        if (SPLIT3) {
            const float* ag1 = a1 + (long long)lrow * lda + koff + lcol0;
            const float* bg1 = b1 + (long long)lrow * ldb + koff + lcol0;
            #pragma unroll
            for (int i = 0; i < 4; i++) {
                cpa16(srow + ALO0 + pb + i * 16u, ag1 + i * 4);
                cpa16(srow + BLO0 + pb + i * 16u, bg1 + i * 4);
            }
        }
    };

    load_chunk(0, 0);
    cpa_commit();
    if (NC > 1) load_chunk(1, 32);
    cpa_commit();

    for (int c = 0; c < NC; c++) {
        cpa_wait1();
        __syncthreads();
        int p = c & 1;
        const float* Ah = sm + (AHI0 >> 2) + p * 4608;
        const float* Al = sm + (ALO0 >> 2) + p * 4608;
        const float* Bh = sm + (BHI0 >> 2) + p * 4608;
        const float* Bl = sm + (BLO0 >> 2) + p * 4608;

        #pragma unroll
        for (int kk = 0; kk < 32; kk += 8) {
            uint32_t ahi[4][4], alo[4][4];
            #pragma unroll
            for (int mi = 0; mi < 4; mi++) {
                int r = wm + mi * 16 + gid;
                ahi[mi][0] = __float_as_uint(Ah[r * 36 + kk + tg]);
                ahi[mi][1] = __float_as_uint(Ah[(r + 8) * 36 + kk + tg]);
                ahi[mi][2] = __float_as_uint(Ah[r * 36 + kk + tg + 4]);
                ahi[mi][3] = __float_as_uint(Ah[(r + 8) * 36 + kk + tg + 4]);
                if (SPLIT3) {
                    alo[mi][0] = __float_as_uint(Al[r * 36 + kk + tg]);
                    alo[mi][1] = __float_as_uint(Al[(r + 8) * 36 + kk + tg]);
                    alo[mi][2] = __float_as_uint(Al[r * 36 + kk + tg + 4]);
                    alo[mi][3] = __float_as_uint(Al[(r + 8) * 36 + kk + tg + 4]);
                }
            }
            #pragma unroll
            for (int ni = 0; ni < 4; ni++) {
                int rn = wn + ni * 8 + gid;
                uint32_t bhi[2], blo[2];
                bhi[0] = __float_as_uint(Bh[rn * 36 + kk + tg]);
                bhi[1] = __float_as_uint(Bh[rn * 36 + kk + tg + 4]);
                if (SPLIT3) {
                    blo[0] = __float_as_uint(Bl[rn * 36 + kk + tg]);
                    blo[1] = __float_as_uint(Bl[rn * 36 + kk + tg + 4]);
                }
                #pragma unroll
                for (int mi = 0; mi < 4; mi++) {
                    mma8(acc[mi][ni], ahi[mi], bhi);
                    if (SPLIT3) {
                        mma8(acc[mi][ni], alo[mi], bhi);
                        mma8(acc[mi][ni], ahi[mi], blo);
                    }
                }
            }
        }
        __syncthreads();
        if (c + 2 < NC) load_chunk(p, (c + 2) * 32);
        cpa_commit();
    }

    // ---------------- epilogue ----------------
    #pragma unroll
    for (int mi = 0; mi < 4; mi++) {
        int r = wm + mi * 16 + gid;
        #pragma unroll
        for (int ni = 0; ni < 4; ni++) {
            int col = wn + ni * 8 + tg * 2;
            #pragma unroll
            for (int half = 0; half < 2; half++) {
                int rr = r + half * 8;
                float v0 = acc[mi][ni][half * 2 + 0];
                float v1 = acc[mi][ni][half * 2 + 1];
                if (EPI == 0) {
                    float* Cp = C + (long long)bz * strC
                              + (long long)(mt * 128 + rr) * ldc + nt * 128 + col;
                    *(float2*)Cp = make_float2(v0, v1);
                } else if (EPI == 1) {
                    float b0v = bias ? bias[nt * 128 + col]     : 0.f;
                    float b1v = bias ? bias[nt * 128 + col + 1] : 0.f;
                    float w0v = alpha * (v0 + b0v);
                    float w1v = alpha * (v1 + b1v);
                    float h0 = rna_tf32f(w0v), h1 = rna_tf32f(w1v);
                    long long off = (long long)bz * strC
                                  + (long long)(mt * 128 + rr) * ldc + nt * 128 + col;
                    *(float2*)(C  + off) = make_float2(h0, h1);
                    *(float2*)(C2 + off) = make_float2(rna_tf32f(w0v - h0),
                                                       rna_tf32f(w1v - h1));
                } else if (EPI == 2) {
                    float bv = BIASM ? bias[mt * 128 + rr] : 0.f;
                    float* Cp = C + (long long)bz * strC
                              + (long long)(mt * 128 + rr) * ldc + nt * 128 + col;
                    *(float2*)Cp = make_float2(rna_tf32f(v0 + bv), rna_tf32f(v1 + bv));
                } else {  // EPI == 3
                    int m = mt * 128 + rr;
                    int bidx = m >> 12, t = m & 4095;
                    int sidx = ((t & 63) << 6) | (t >> 6);
                    long long i0 = ((long long)bidx << 20)
                                 + ((long long)(nt * 128 + col) << 12) + sidx;
                    long long i1 = i0 + 4096;
                    C[i0] = xres[i0] + v0 + bias[nt * 128 + col];
                    C[i1] = xres[i1] + v1 + bias[nt * 128 + col + 1];
                }
            }
        }
    }
}

// ---------------- masked softmax, variable length, register-cached ------------
__global__ __launch_bounds__(256) void softmax_kernel() {
    int row = blockIdx.x;
    int p = row & 4095;
    int wq = p >> 6;
    int L = (wq + 1) << 6;
    float* S = g_s + (size_t)row * HWT;
    int tid = threadIdx.x;
    __shared__ float red[8];
    const float NEG = -1e30f;

    float vals[16];
    float mx = NEG;
    #pragma unroll
    for (int it = 0; it < 16; it++) {
        int j = it * 256 + tid;
        float v = (j < L) ? S[j] : NEG;
        vals[it] = v;
        mx = fmaxf(mx, v);
    }
    #pragma unroll
    for (int o = 16; o > 0; o >>= 1)
        mx = fmaxf(mx, __shfl_xor_sync(0xffffffffu, mx, o));
    if ((tid & 31) == 0) red[tid >> 5] = mx;
    __syncthreads();
    mx = red[0];
    #pragma unroll
    for (int i = 1; i < 8; i++) mx = fmaxf(mx, red[i]);
    __syncthreads();

    float sum = 0.f;
    #pragma unroll
    for (int it = 0; it < 16; it++) {
        float e = __expf(vals[it] - mx);
        vals[it] = e;
        sum += e;
    }
    #pragma unroll
    for (int o = 16; o > 0; o >>= 1)
        sum += __shfl_xor_sync(0xffffffffu, sum, o);
    if ((tid & 31) == 0) red[tid >> 5] = sum;
    __syncthreads();
    sum = 0.f;
    #pragma unroll
    for (int i = 0; i < 8; i++) sum += red[i];

    float inv = 1.f / sum;
    #pragma unroll
    for (int it = 0; it < 16; it++) {
        int j = it * 256 + tid;
        if (j < L) S[j] = rna_tf32f(vals[it] * inv);
    }
    if (!(wq & 1) && tid < 64) S[L + tid] = 0.f;   // pad to 128-tile boundary
}

// ---------------- launch ------------------------------------------------------
extern "C" void kernel_launch(void* const* d_in, const int* in_sizes, int n_in,
                              void* d_out, int out_size) {
    (void)in_sizes; (void)n_in; (void)out_size;
    const float* x   = (const float*)d_in[0];
    const float* gnw = (const float*)d_in[1];
    const float* gnb = (const float*)d_in[2];
    const float* w0  = (const float*)d_in[3];
    const float* b0  = (const float*)d_in[4];
    const float* w1  = (const float*)d_in[5];
    const float* b1  = (const float*)d_in[6];
    const float* w2  = (const float*)d_in[7];
    const float* b2  = (const float*)d_in[8];
    const float* w3  = (const float*)d_in[9];
    const float* b3  = (const float*)d_in[10];
    float* out = (float*)d_out;

    const int SM_SPLIT = 147456;   // 8 tiles
    const int SM_PLAIN = 73728;    // 4 tiles
    cudaFuncSetAttribute(mma_nt_kernel<true, false, false, 1, false>,
                         cudaFuncAttributeMaxDynamicSharedMemorySize, SM_SPLIT);
    cudaFuncSetAttribute(mma_nt_kernel<true, false, false, 2, true>,
                         cudaFuncAttributeMaxDynamicSharedMemorySize, SM_SPLIT);
    cudaFuncSetAttribute(mma_nt_kernel<true, true, false, 0, false>,
                         cudaFuncAttributeMaxDynamicSharedMemorySize, SM_SPLIT);
    cudaFuncSetAttribute(mma_nt_kernel<false, false, true, 1, false>,
                         cudaFuncAttributeMaxDynamicSharedMemorySize, SM_PLAIN);
    cudaFuncSetAttribute(mma_nt_kernel<true, false, false, 3, false>,
                         cudaFuncAttributeMaxDynamicSharedMemorySize, SM_SPLIT);

    void *p0, *p1, *p2, *p3, *p4, *p5, *p6, *p7, *p8, *p9, *p10, *p11;
    cudaGetSymbolAddress(&p0,  g_hn_hi);
    cudaGetSymbolAddress(&p1,  g_hn_lo);
    cudaGetSymbolAddress(&p2,  g_q_hi);
    cudaGetSymbolAddress(&p3,  g_q_lo);
    cudaGetSymbolAddress(&p4,  g_k_hi);
    cudaGetSymbolAddress(&p5,  g_k_lo);
    cudaGetSymbolAddress(&p6,  g_vt);
    cudaGetSymbolAddress(&p7,  g_h_hi);
    cudaGetSymbolAddress(&p8,  g_h_lo);
    cudaGetSymbolAddress(&p9,  g_wt_hi);
    cudaGetSymbolAddress(&p10, g_wt_lo);
    cudaGetSymbolAddress(&p11, g_s);
    float* hnh = (float*)p0;  float* hnl = (float*)p1;
    float* qh  = (float*)p2;  float* ql  = (float*)p3;
    float* kh  = (float*)p4;  float* kl  = (float*)p5;
    float* vt  = (float*)p6;
    float* hh  = (float*)p7;  float* hl  = (float*)p8;
    float* wth = (float*)p9;  float* wtl = (float*)p10;
    float* s   = (float*)p11;

    const long long QKV_STR = (long long)HWT * CCH;
    const long long S_STR   = (long long)HWT * HWT;
    const int WSZ = CCH * CCH;

    // 1. GroupNorm (permuted, split)
    groupnorm_kernel<<<512, 256>>>(x, gnw, gnb);

    // 2. weight prep (transpose + split), 4 matrices
    dim3 wb(32, 32), wg(8, 8);
    wprep_kernel<<<wg, wb>>>(w0, wth + 0 * WSZ, wtl + 0 * WSZ);
    wprep_kernel<<<wg, wb>>>(w1, wth + 1 * WSZ, wtl + 1 * WSZ);
    wprep_kernel<<<wg, wb>>>(w2, wth + 2 * WSZ, wtl + 2 * WSZ);
    wprep_kernel<<<wg, wb>>>(w3, wth + 3 * WSZ, wtl + 3 * WSZ);

    // 3. Q, K projections (split outputs; Q scaled by 1/16)
    dim3 gq(2, 128, 1);
    mma_nt_kernel<true, false, false, 1, false><<<gq, 256, SM_SPLIT>>>(
        hnh, hnl, wth + 0 * WSZ, wtl + 0 * WSZ, qh, ql, b0, nullptr,
        0.0625f, CCH, CCH, CCH, CCH, 0, 0, 0);
    mma_nt_kernel<true, false, false, 1, false><<<gq, 256, SM_SPLIT>>>(
        hnh, hnl, wth + 1 * WSZ, wtl + 1 * WSZ, kh, kl, b1, nullptr,
        1.0f, CCH, CCH, CCH, CCH, 0, 0, 0);

    // 4. V projection, transposed output: C'[c][p] = W2^T x HN^T
    dim3 gv(32, 2, 4);
    mma_nt_kernel<true, false, false, 2, true><<<gv, 256, SM_SPLIT>>>(
        wth + 2 * WSZ, wtl + 2 * WSZ, hnh, hnl, vt, nullptr, b2, nullptr,
        1.0f, CCH, CCH, HWT, CCH, 0, QKV_STR, QKV_STR);

    // 5. Scores S = Q*K^T (3xTF32, triangular tiles)
    dim3 gs(32, 32, 4);
    mma_nt_kernel<true, true, false, 0, false><<<gs, 256, SM_SPLIT>>>(
        qh, ql, kh, kl, s, nullptr, nullptr, nullptr,
        1.0f, CCH, CCH, HWT, CCH, QKV_STR, QKV_STR, S_STR);

    // 6. Softmax
    softmax_kernel<<<NTOK, 256>>>();

    // 7. H = P * V^T (causal K range, split output for final proj)
    dim3 gp(2, 32, 4);
    mma_nt_kernel<false, false, true, 1, false><<<gp, 256, SM_PLAIN>>>(
        s, nullptr, vt, nullptr, hh, hl, nullptr, nullptr,
        1.0f, HWT, HWT, CCH, 0, S_STR, QKV_STR, QKV_STR);

    // 8. out = x + H*w3 + b3 (scatter + unpermute)
    dim3 gf(2, 128, 1);
    mma_nt_kernel<true, false, false, 3, false><<<gf, 256, SM_SPLIT>>>(
        hh, hl, wth + 3 * WSZ, wtl + 3 * WSZ, out, nullptr, b3, x,
        1.0f, CCH, CCH, 0, CCH, 0, 0, 0);
}

// round 7
// speedup vs baseline: 2.1383x; 2.1383x over previous
#include <cuda_runtime.h>
#include <cuda_fp16.h>
#include <math.h>
#include <stdint.h>

// Problem dims
#define BCH 4
#define CCH 256
#define HWT 4096          // H*W = 64*64
#define NTOK 16384        // B*HW

// Token order inside each batch is PERMUTED: p = w*64 + h. Causal mask becomes
// block-lower-triangular at 64-token granularity, diagonal fully allowed.

// ---------------- scratch ------------------------------------------------------
__device__ __align__(256) __half g_hn_hi[(size_t)NTOK * CCH];
__device__ __align__(256) __half g_hn_lo[(size_t)NTOK * CCH];
__device__ __align__(256) __half g_q_hi [(size_t)NTOK * CCH];
__device__ __align__(256) __half g_q_lo [(size_t)NTOK * CCH];
__device__ __align__(256) __half g_k_hi [(size_t)NTOK * CCH];
__device__ __align__(256) __half g_k_lo [(size_t)NTOK * CCH];
__device__ __align__(256) __half g_vt   [(size_t)NTOK * CCH];   // [b][c][p]
__device__ __align__(256) __half g_h_hi [(size_t)NTOK * CCH];
__device__ __align__(256) __half g_h_lo [(size_t)NTOK * CCH];
__device__ __align__(256) __half g_wt_hi[4 * CCH * CCH];        // transposed wts
__device__ __align__(256) __half g_wt_lo[4 * CCH * CCH];
__device__ __align__(256) __half g_p    [(size_t)BCH * HWT * HWT];  // P fp16
__device__ __align__(256) float  g_s    [(size_t)BCH * HWT * HWT];  // S fp32

// ---------------- helpers -----------------------------------------------------
__device__ __forceinline__ uint32_t smem_u32(const void* p) {
    uint32_t a;
    asm("{ .reg .u64 t; cvta.to.shared.u64 t, %1; cvt.u32.u64 %0, t; }"
        : "=r"(a) : "l"(p));
    return a;
}
__device__ __forceinline__ void cpa16(uint32_t dst, const void* src) {
    asm volatile("cp.async.cg.shared.global [%0], [%1], 16;"
                 :: "r"(dst), "l"(src));
}
__device__ __forceinline__ void cpa_commit() {
    asm volatile("cp.async.commit_group;" ::: "memory");
}
__device__ __forceinline__ void cpa_wait1() {
    asm volatile("cp.async.wait_group 1;" ::: "memory");
}
// m16n8k16 fp16 MMA, fp32 accumulate
__device__ __forceinline__ void mma16(float* c, const uint32_t* a, const uint32_t* b) {
    asm volatile("mma.sync.aligned.m16n8k16.row.col.f32.f16.f16.f32 "
        "{%0,%1,%2,%3}, {%4,%5,%6,%7}, {%8,%9}, {%0,%1,%2,%3};"
        : "+f"(c[0]), "+f"(c[1]), "+f"(c[2]), "+f"(c[3])
        : "r"(a[0]), "r"(a[1]), "r"(a[2]), "r"(a[3]), "r"(b[0]), "r"(b[1]));
}

// ---------------- GroupNorm -> permuted hn (fp16 hi/lo split) ------------------
__global__ __launch_bounds__(256) void groupnorm_kernel(
    const float* __restrict__ x,
    const float* __restrict__ gnw,
    const float* __restrict__ gnb)
{
    __shared__ float tile[CCH][33];
    __shared__ float sw[CCH];
    __shared__ float sb[CCH];
    int tid = threadIdx.x;
    int b = blockIdx.x >> 7;
    int hwbase = (blockIdx.x & 127) << 5;
    int tx = tid & 31, ty = tid >> 5;

    const float* xb = x + (size_t)b * CCH * HWT;
    for (int c = ty; c < CCH; c += 8)
        tile[c][tx] = xb[(size_t)c * HWT + hwbase + tx];
    sw[tid] = gnw[tid];
    sb[tid] = gnb[tid];
    __syncthreads();

    int tok = tx;
    #pragma unroll
    for (int gi = 0; gi < 4; gi++) {
        int c0 = (ty + gi * 8) * 8;
        float s = 0.f, ss = 0.f;
        #pragma unroll
        for (int j = 0; j < 8; j++) {
            float v = tile[c0 + j][tok];
            s += v; ss += v * v;
        }
        float m   = s * 0.125f;
        float var = ss * 0.125f - m * m;
        float r   = rsqrtf(var + 1e-6f);
        #pragma unroll
        for (int j = 0; j < 8; j++) {
            int c = c0 + j;
            tile[c][tok] = (tile[c][tok] - m) * r * sw[c] + sb[c];
        }
    }
    __syncthreads();

    int h = hwbase >> 6;
    __half* hh = g_hn_hi + ((size_t)b << 12) * CCH;
    __half* hl = g_hn_lo + ((size_t)b << 12) * CCH;
    for (int it = 0; it < 32; it++) {
        int w = (hwbase + it) & 63;
        int p = (w << 6) | h;
        float v = tile[tid][it];
        __half hi = __float2half_rn(v);
        hh[(size_t)p * CCH + tid] = hi;
        hl[(size_t)p * CCH + tid] = __float2half_rn(v - __half2float(hi));
    }
}

// ---------------- weight prep: transpose + fp16 hi/lo split -------------------
__global__ void wprep_kernel(const float* __restrict__ w,
                             __half* __restrict__ whi,
                             __half* __restrict__ wlo)
{
    __shared__ float t[32][33];
    int tx = threadIdx.x, ty = threadIdx.y;
    int bx = blockIdx.x * 32, by = blockIdx.y * 32;
    t[ty][tx] = w[(by + ty) * CCH + bx + tx];
    __syncthreads();
    float v = t[tx][ty];
    __half hi = __float2half_rn(v);
    whi[(bx + ty) * CCH + by + tx] = hi;
    wlo[(bx + ty) * CCH + by + tx] = __float2half_rn(v - __half2float(hi));
}

// ---------------- unified fp16 tensor-core NT GEMM ----------------------------
// C[128x128] tiles; A [M][K] rm, B [N][K] rm, all fp16.
// SPLIT: 2-term hi/lo (3 mmas: hh, lh, hl) ~ fp32. TRI: scores skip nt>mt.
// CAUSALK: PV (mt reversed, Ktile=128*(mt+1)).
// EPI 0: Cf=acc (f32). 1: fp16 hi/lo split store of alpha*(acc+bias[n]).
//     2: Ch=rn(acc+bias[m]) (BIASM). 3: Cf = x + acc + bias[n], unperm scatter.
template <bool SPLIT, bool TRI, bool CAUSALK, int EPI, bool BIASM>
__global__ __launch_bounds__(256, 2) void mma_fp16_kernel(
    const __half* __restrict__ A0, const __half* __restrict__ A1,
    const __half* __restrict__ B0, const __half* __restrict__ B1,
    float* __restrict__ Cf, __half* __restrict__ Ch, __half* __restrict__ Ch2,
    const float* __restrict__ bias, const float* __restrict__ xres,
    float alpha,
    int lda, int ldb, int ldc, int Kfull,
    long long strA, long long strB, long long strC)
{
    int nt = blockIdx.x, bz = blockIdx.z;
    int mt;
    if (TRI) {
        mt = blockIdx.y;
        if (nt > mt) return;
    } else if (CAUSALK) {
        mt = (int)gridDim.y - 1 - (int)blockIdx.y;
    } else {
        mt = blockIdx.y;
    }
    int Ktile = CAUSALK ? 128 * (mt + 1) : Kfull;

    extern __shared__ uint32_t smw[];
    uint32_t sbase = smem_u32(smw);

    int tid = threadIdx.x;
    int lane = tid & 31, wid = tid >> 5;
    int wm = (wid >> 2) * 64, wn = (wid & 3) * 32;
    int gid = lane >> 2, tg = lane & 3;

    const __half* a0 = A0 + (long long)bz * strA + (long long)mt * 128 * lda;
    const __half* b0 = B0 + (long long)bz * strB + (long long)nt * 128 * ldb;
    const __half* a1 = SPLIT ? A1 + (long long)bz * strA + (long long)mt * 128 * lda : nullptr;
    const __half* b1 = SPLIT ? B1 + (long long)bz * strB + (long long)nt * 128 * ldb : nullptr;

    float acc[4][4][4];
    #pragma unroll
    for (int mi = 0; mi < 4; mi++)
        #pragma unroll
        for (int ni = 0; ni < 4; ni++)
            #pragma unroll
            for (int e = 0; e < 4; e++) acc[mi][ni][e] = 0.f;

    // smem: tiles of 128 rows x 20 uint32 (32 halves data + pad) = 10240 B
    const uint32_t TB = 10240u;
    const uint32_t BUF = SPLIT ? 4 * TB : 2 * TB;
    const uint32_t BOFF = SPLIT ? 2 * TB : TB;   // B-hi tile offset in buffer

    const int NC = Ktile >> 5;

    auto load_chunk = [&](int p, int koff) {
        uint32_t pb = sbase + (uint32_t)p * BUF;
        #pragma unroll
        for (int j = 0; j < 2; j++) {
            int v = tid + j * 256;
            int row = v >> 2, c16 = v & 3;
            uint32_t o = (uint32_t)row * 80u + (uint32_t)c16 * 16u;
            const __half* sA0 = a0 + (long long)row * lda + koff + c16 * 8;
            const __half* sB0 = b0 + (long long)row * ldb + koff + c16 * 8;
            cpa16(pb + o, sA0);
            cpa16(pb + BOFF + o, sB0);
            if (SPLIT) {
                const __half* sA1 = a1 + (long long)row * lda + koff + c16 * 8;
                const __half* sB1 = b1 + (long long)row * ldb + koff + c16 * 8;
                cpa16(pb + TB + o, sA1);
                cpa16(pb + 3 * TB + o, sB1);
            }
        }
    };

    load_chunk(0, 0);
    cpa_commit();
    if (NC > 1) load_chunk(1, 32);
    cpa_commit();

    for (int c = 0; c < NC; c++) {
        cpa_wait1();
        __syncthreads();
        int p = c & 1;
        uint32_t pbw = (uint32_t)p * (BUF >> 2);
        const uint32_t* Ah = smw + pbw;
        const uint32_t* Al = smw + pbw + (TB >> 2);
        const uint32_t* Bh = smw + pbw + (BOFF >> 2);
        const uint32_t* Bl = smw + pbw + 3 * (TB >> 2);

        #pragma unroll
        for (int blk = 0; blk < 2; blk++) {
            int kb = blk * 8 + tg;
            uint32_t ahi[4][4], alo[4][4];
            #pragma unroll
            for (int mi = 0; mi < 4; mi++) {
                int r = wm + mi * 16 + gid;
                ahi[mi][0] = Ah[r * 20 + kb];
                ahi[mi][1] = Ah[(r + 8) * 20 + kb];
                ahi[mi][2] = Ah[r * 20 + kb + 4];
                ahi[mi][3] = Ah[(r + 8) * 20 + kb + 4];
                if (SPLIT) {
                    alo[mi][0] = Al[r * 20 + kb];
                    alo[mi][1] = Al[(r + 8) * 20 + kb];
                    alo[mi][2] = Al[r * 20 + kb + 4];
                    alo[mi][3] = Al[(r + 8) * 20 + kb + 4];
                }
            }
            #pragma unroll
            for (int ni = 0; ni < 4; ni++) {
                int rn = wn + ni * 8 + gid;
                uint32_t bhi[2], blo[2];
                bhi[0] = Bh[rn * 20 + kb];
                bhi[1] = Bh[rn * 20 + kb + 4];
                if (SPLIT) {
                    blo[0] = Bl[rn * 20 + kb];
                    blo[1] = Bl[rn * 20 + kb + 4];
                }
                #pragma unroll
                for (int mi = 0; mi < 4; mi++) {
                    mma16(acc[mi][ni], ahi[mi], bhi);
                    if (SPLIT) {
                        mma16(acc[mi][ni], alo[mi], bhi);
                        mma16(acc[mi][ni], ahi[mi], blo);
                    }
                }
            }
        }
        __syncthreads();
        if (c + 2 < NC) load_chunk(p, (c + 2) * 32);
        cpa_commit();
    }

    // ---------------- epilogue ----------------
    #pragma unroll
    for (int mi = 0; mi < 4; mi++) {
        int r = wm + mi * 16 + gid;
        #pragma unroll
        for (int ni = 0; ni < 4; ni++) {
            int col = wn + ni * 8 + tg * 2;
            #pragma unroll
            for (int half_ = 0; half_ < 2; half_++) {
                int rr = r + half_ * 8;
                float v0 = acc[mi][ni][half_ * 2 + 0];
                float v1 = acc[mi][ni][half_ * 2 + 1];
                if (EPI == 0) {
                    float* Cp = Cf + (long long)bz * strC
                              + (long long)(mt * 128 + rr) * ldc + nt * 128 + col;
                    *(float2*)Cp = make_float2(v0, v1);
                } else if (EPI == 1) {
                    float b0v = bias ? bias[nt * 128 + col]     : 0.f;
                    float b1v = bias ? bias[nt * 128 + col + 1] : 0.f;
                    float w0v = alpha * (v0 + b0v);
                    float w1v = alpha * (v1 + b1v);
                    __half h0 = __float2half_rn(w0v);
                    __half h1 = __float2half_rn(w1v);
                    __half l0 = __float2half_rn(w0v - __half2float(h0));
                    __half l1 = __float2half_rn(w1v - __half2float(h1));
                    long long off = (long long)bz * strC
                                  + (long long)(mt * 128 + rr) * ldc + nt * 128 + col;
                    *(__half2*)(Ch  + off) = __halves2half2(h0, h1);
                    *(__half2*)(Ch2 + off) = __halves2half2(l0, l1);
                } else if (EPI == 2) {
                    float bv = BIASM ? bias[mt * 128 + rr] : 0.f;
                    __half* Cp = Ch + (long long)bz * strC
                               + (long long)(mt * 128 + rr) * ldc + nt * 128 + col;
                    *(__half2*)Cp = __halves2half2(__float2half_rn(v0 + bv),
                                                   __float2half_rn(v1 + bv));
                } else {  // EPI == 3
                    int m = mt * 128 + rr;
                    int bidx = m >> 12, t = m & 4095;
                    int sidx = ((t & 63) << 6) | (t >> 6);
                    long long i0 = ((long long)bidx << 20)
                                 + ((long long)(nt * 128 + col) << 12) + sidx;
                    long long i1 = i0 + 4096;
                    Cf[i0] = xres[i0] + v0 + bias[nt * 128 + col];
                    Cf[i1] = xres[i1] + v1 + bias[nt * 128 + col + 1];
                }
            }
        }
    }
}

// ---------------- masked softmax: fp32 S in, fp16 P out -----------------------
__global__ __launch_bounds__(256) void softmax_kernel() {
    int row = blockIdx.x;
    int p = row & 4095;
    int wq = p >> 6;
    int L = (wq + 1) << 6;
    const float* S = g_s + (size_t)row * HWT;
    __half* P = g_p + (size_t)row * HWT;
    int tid = threadIdx.x;
    __shared__ float red[8];
    const float NEG = -1e30f;

    float vals[16];
    float mx = NEG;
    #pragma unroll
    for (int it = 0; it < 16; it++) {
        int j = it * 256 + tid;
        float v = (j < L) ? S[j] : NEG;
        vals[it] = v;
        mx = fmaxf(mx, v);
    }
    #pragma unroll
    for (int o = 16; o > 0; o >>= 1)
        mx = fmaxf(mx, __shfl_xor_sync(0xffffffffu, mx, o));
    if ((tid & 31) == 0) red[tid >> 5] = mx;
    __syncthreads();
    mx = red[0];
    #pragma unroll
    for (int i = 1; i < 8; i++) mx = fmaxf(mx, red[i]);
    __syncthreads();

    float sum = 0.f;
    #pragma unroll
    for (int it = 0; it < 16; it++) {
        float e = __expf(vals[it] - mx);
        vals[it] = e;
        sum += e;
    }
    #pragma unroll
    for (int o = 16; o > 0; o >>= 1)
        sum += __shfl_xor_sync(0xffffffffu, sum, o);
    if ((tid & 31) == 0) red[tid >> 5] = sum;
    __syncthreads();
    sum = 0.f;
    #pragma unroll
    for (int i = 0; i < 8; i++) sum += red[i];

    float inv = 1.f / sum;
    #pragma unroll
    for (int it = 0; it < 16; it++) {
        int j = it * 256 + tid;
        if (j < L) P[j] = __float2half_rn(vals[it] * inv);
    }
    if (!(wq & 1) && tid < 64) P[L + tid] = __float2half_rn(0.f);
}

// ---------------- launch ------------------------------------------------------
extern "C" void kernel_launch(void* const* d_in, const int* in_sizes, int n_in,
                              void* d_out, int out_size) {
    (void)in_sizes; (void)n_in; (void)out_size;
    const float* x   = (const float*)d_in[0];
    const float* gnw = (const float*)d_in[1];
    const float* gnb = (const float*)d_in[2];
    const float* w0  = (const float*)d_in[3];
    const float* b0  = (const float*)d_in[4];
    const float* w1  = (const float*)d_in[5];
    const float* b1  = (const float*)d_in[6];
    const float* w2  = (const float*)d_in[7];
    const float* b2  = (const float*)d_in[8];
    const float* w3  = (const float*)d_in[9];
    const float* b3  = (const float*)d_in[10];
    float* out = (float*)d_out;

    const int SM_SPLIT = 81920;   // 8 fp16 tiles (4 per buffer x2)
    const int SM_SINGLE = 40960;  // 4 fp16 tiles
    cudaFuncSetAttribute(mma_fp16_kernel<true, false, false, 1, false>,
                         cudaFuncAttributeMaxDynamicSharedMemorySize, SM_SPLIT);
    cudaFuncSetAttribute(mma_fp16_kernel<true, false, false, 2, true>,
                         cudaFuncAttributeMaxDynamicSharedMemorySize, SM_SPLIT);
    cudaFuncSetAttribute(mma_fp16_kernel<true, true, false, 0, false>,
                         cudaFuncAttributeMaxDynamicSharedMemorySize, SM_SPLIT);
    cudaFuncSetAttribute(mma_fp16_kernel<false, false, true, 1, false>,
                         cudaFuncAttributeMaxDynamicSharedMemorySize, SM_SINGLE);
    cudaFuncSetAttribute(mma_fp16_kernel<true, false, false, 3, false>,
                         cudaFuncAttributeMaxDynamicSharedMemorySize, SM_SPLIT);

    void *p0, *p1, *p2, *p3, *p4, *p5, *p6, *p7, *p8, *p9, *p10, *p11, *p12;
    cudaGetSymbolAddress(&p0,  g_hn_hi);
    cudaGetSymbolAddress(&p1,  g_hn_lo);
    cudaGetSymbolAddress(&p2,  g_q_hi);
    cudaGetSymbolAddress(&p3,  g_q_lo);
    cudaGetSymbolAddress(&p4,  g_k_hi);
    cudaGetSymbolAddress(&p5,  g_k_lo);
    cudaGetSymbolAddress(&p6,  g_vt);
    cudaGetSymbolAddress(&p7,  g_h_hi);
    cudaGetSymbolAddress(&p8,  g_h_lo);
    cudaGetSymbolAddress(&p9,  g_wt_hi);
    cudaGetSymbolAddress(&p10, g_wt_lo);
    cudaGetSymbolAddress(&p11, g_p);
    cudaGetSymbolAddress(&p12, g_s);
    __half* hnh = (__half*)p0;  __half* hnl = (__half*)p1;
    __half* qh  = (__half*)p2;  __half* ql  = (__half*)p3;
    __half* kh  = (__half*)p4;  __half* kl  = (__half*)p5;
    __half* vt  = (__half*)p6;
    __half* hh  = (__half*)p7;  __half* hl  = (__half*)p8;
    __half* wth = (__half*)p9;  __half* wtl = (__half*)p10;
    __half* pp  = (__half*)p11;
    float*  s   = (float*)p12;

    const long long QKV_STR = (long long)HWT * CCH;
    const long long S_STR   = (long long)HWT * HWT;
    const int WSZ = CCH * CCH;

    // 1. GroupNorm (permuted, fp16 split)
    groupnorm_kernel<<<512, 256>>>(x, gnw, gnb);

    // 2. weight prep (transpose + fp16 split)
    dim3 wb(32, 32), wg(8, 8);
    wprep_kernel<<<wg, wb>>>(w0, wth + 0 * WSZ, wtl + 0 * WSZ);
    wprep_kernel<<<wg, wb>>>(w1, wth + 1 * WSZ, wtl + 1 * WSZ);
    wprep_kernel<<<wg, wb>>>(w2, wth + 2 * WSZ, wtl + 2 * WSZ);
    wprep_kernel<<<wg, wb>>>(w3, wth + 3 * WSZ, wtl + 3 * WSZ);

    // 3. Q, K projections (fp16 2-term; Q scaled by 1/16; split outputs)
    dim3 gq(2, 128, 1);
    mma_fp16_kernel<true, false, false, 1, false><<<gq, 256, SM_SPLIT>>>(
        hnh, hnl, wth + 0 * WSZ, wtl + 0 * WSZ, nullptr, qh, ql, b0, nullptr,
        0.0625f, CCH, CCH, CCH, CCH, 0, 0, 0);
    mma_fp16_kernel<true, false, false, 1, false><<<gq, 256, SM_SPLIT>>>(
        hnh, hnl, wth + 1 * WSZ, wtl + 1 * WSZ, nullptr, kh, kl, b1, nullptr,
        1.0f, CCH, CCH, CCH, CCH, 0, 0, 0);

    // 4. V projection, transposed output: vt[c][p] = W2^T x HN^T
    dim3 gv(32, 2, 4);
    mma_fp16_kernel<true, false, false, 2, true><<<gv, 256, SM_SPLIT>>>(
        wth + 2 * WSZ, wtl + 2 * WSZ, hnh, hnl, nullptr, vt, nullptr, b2, nullptr,
        1.0f, CCH, CCH, HWT, CCH, 0, QKV_STR, QKV_STR);

    // 5. Scores S = Q*K^T (fp16 2-term ~ fp32; triangular tiles only)
    dim3 gs(32, 32, 4);
    mma_fp16_kernel<true, true, false, 0, false><<<gs, 256, SM_SPLIT>>>(
        qh, ql, kh, kl, s, nullptr, nullptr, nullptr, nullptr,
        1.0f, CCH, CCH, HWT, CCH, QKV_STR, QKV_STR, S_STR);

    // 6. Softmax (fp32 in, fp16 P out, pad zero-fill)
    softmax_kernel<<<NTOK, 256>>>();

    // 7. H = P * V^T (single fp16, causal K range; fp16 split output)
    dim3 gp(2, 32, 4);
    mma_fp16_kernel<false, false, true, 1, false><<<gp, 256, SM_SINGLE>>>(
        pp, nullptr, vt, nullptr, nullptr, hh, hl, nullptr, nullptr,
        1.0f, HWT, HWT, CCH, 0, S_STR, QKV_STR, QKV_STR);

    // 8. out = x + H*w3 + b3 (scatter + unpermute)
    dim3 gf(2, 128, 1);
    mma_fp16_kernel<true, false, false, 3, false><<<gf, 256, SM_SPLIT>>>(
        hh, hl, wth + 3 * WSZ, wtl + 3 * WSZ, out, nullptr, nullptr, b3, x,
        1.0f, CCH, CCH, 0, CCH, 0, 0, 0);
}

// round 8
// speedup vs baseline: 2.9796x; 1.3935x over previous
#include <cuda_runtime.h>
#include <cuda_fp16.h>
#include <math.h>
#include <stdint.h>

// Problem dims
#define BCH 4
#define CCH 256
#define HWT 4096          // H*W = 64*64
#define NTOK 16384        // B*HW

// Token order inside each batch is PERMUTED: p = w*64 + h. Causal mask becomes
// block-lower-triangular at 64-token granularity, diagonal fully allowed.

// ---------------- scratch ------------------------------------------------------
__device__ __align__(256) __half g_hn  [(size_t)NTOK * CCH];         // fp16 single
__device__ __align__(256) __half g_qk  [(size_t)NTOK * 2 * CCH];     // [tok][512]: Q|K
__device__ __align__(256) __half g_vt  [(size_t)NTOK * CCH];         // [b][c][p]
__device__ __align__(256) __half g_h_hi[(size_t)NTOK * CCH];
__device__ __align__(256) __half g_h_lo[(size_t)NTOK * CCH];
__device__ __align__(256) __half g_wqk [2 * CCH * CCH];              // [512][256] w0t/16 | w1t
__device__ __align__(256) __half g_w2t [CCH * CCH];
__device__ __align__(256) __half g_w3hi[CCH * CCH];
__device__ __align__(256) __half g_w3lo[CCH * CCH];
__device__ __align__(256) float  g_bqk [2 * CCH];                    // b0/16 | b1
__device__ __align__(256) __half g_s   [(size_t)BCH * HWT * HWT];    // S then P (in place)

// ---------------- helpers -----------------------------------------------------
__device__ __forceinline__ uint32_t smem_u32(const void* p) {
    uint32_t a;
    asm("{ .reg .u64 t; cvta.to.shared.u64 t, %1; cvt.u32.u64 %0, t; }"
        : "=r"(a) : "l"(p));
    return a;
}
__device__ __forceinline__ void cpa16(uint32_t dst, const void* src) {
    asm volatile("cp.async.cg.shared.global [%0], [%1], 16;"
                 :: "r"(dst), "l"(src));
}
__device__ __forceinline__ void cpa_commit() {
    asm volatile("cp.async.commit_group;" ::: "memory");
}
__device__ __forceinline__ void cpa_wait1() {
    asm volatile("cp.async.wait_group 1;" ::: "memory");
}
// m16n8k16 fp16 MMA, fp32 accumulate
__device__ __forceinline__ void mma16(float* c, const uint32_t* a, const uint32_t* b) {
    asm volatile("mma.sync.aligned.m16n8k16.row.col.f32.f16.f16.f32 "
        "{%0,%1,%2,%3}, {%4,%5,%6,%7}, {%8,%9}, {%0,%1,%2,%3};"
        : "+f"(c[0]), "+f"(c[1]), "+f"(c[2]), "+f"(c[3])
        : "r"(a[0]), "r"(a[1]), "r"(a[2]), "r"(a[3]), "r"(b[0]), "r"(b[1]));
}

// ---------------- GroupNorm -> permuted hn (fp16 single) ----------------------
__global__ __launch_bounds__(256) void groupnorm_kernel(
    const float* __restrict__ x,
    const float* __restrict__ gnw,
    const float* __restrict__ gnb)
{
    __shared__ float tile[CCH][33];
    __shared__ float sw[CCH];
    __shared__ float sb[CCH];
    int tid = threadIdx.x;
    int b = blockIdx.x >> 7;
    int hwbase = (blockIdx.x & 127) << 5;
    int tx = tid & 31, ty = tid >> 5;

    const float* xb = x + (size_t)b * CCH * HWT;
    for (int c = ty; c < CCH; c += 8)
        tile[c][tx] = xb[(size_t)c * HWT + hwbase + tx];
    sw[tid] = gnw[tid];
    sb[tid] = gnb[tid];
    __syncthreads();

    int tok = tx;
    #pragma unroll
    for (int gi = 0; gi < 4; gi++) {
        int c0 = (ty + gi * 8) * 8;
        float s = 0.f, ss = 0.f;
        #pragma unroll
        for (int j = 0; j < 8; j++) {
            float v = tile[c0 + j][tok];
            s += v; ss += v * v;
        }
        float m   = s * 0.125f;
        float var = ss * 0.125f - m * m;
        float r   = rsqrtf(var + 1e-6f);
        #pragma unroll
        for (int j = 0; j < 8; j++) {
            int c = c0 + j;
            tile[c][tok] = (tile[c][tok] - m) * r * sw[c] + sb[c];
        }
    }
    __syncthreads();

    int h = hwbase >> 6;
    __half* hh = g_hn + ((size_t)b << 12) * CCH;
    for (int it = 0; it < 32; it++) {
        int w = (hwbase + it) & 63;
        int p = (w << 6) | h;
        hh[(size_t)p * CCH + tid] = __float2half_rn(tile[tid][it]);
    }
}

// ---------------- weight prep: all 4 transposes + bias concat, one kernel -----
__global__ void wprep_all(const float* __restrict__ w0, const float* __restrict__ b0,
                          const float* __restrict__ w1, const float* __restrict__ b1,
                          const float* __restrict__ w2, const float* __restrict__ w3)
{
    __shared__ float t[32][33];
    int bid = blockIdx.x;            // 0..255
    int mat = bid >> 6;
    int tile_ = bid & 63;
    int bx = (tile_ & 7) * 32, by = (tile_ >> 3) * 32;
    int tx = threadIdx.x, ty = threadIdx.y;

    const float* w = (mat == 0) ? w0 : (mat == 1) ? w1 : (mat == 2) ? w2 : w3;
    t[ty][tx] = w[(by + ty) * CCH + bx + tx];
    __syncthreads();
    float v = t[tx][ty];             // = w[(by+tx)][bx+ty] -> dest[r=bx+ty][c=by+tx]
    int dst = (bx + ty) * CCH + by + tx;
    if (mat == 0) {
        g_wqk[dst] = __float2half_rn(v * 0.0625f);
    } else if (mat == 1) {
        g_wqk[CCH * CCH + dst] = __float2half_rn(v);
    } else if (mat == 2) {
        g_w2t[dst] = __float2half_rn(v);
    } else {
        __half hi = __float2half_rn(v);
        g_w3hi[dst] = hi;
        g_w3lo[dst] = __float2half_rn(v - __half2float(hi));
    }
    if (bid == 0) {
        int t0 = ty * 32 + tx;
        if (t0 < 256)      g_bqk[t0] = b0[t0] * 0.0625f;
        else if (t0 < 512) g_bqk[t0] = b1[t0 - 256];
    }
}

// ---------------- unified fp16 tensor-core NT GEMM ----------------------------
// C[128x128] tiles; A [M][K] rm, B [N][K] rm, fp16.
// SPLIT: 2-term hi/lo (3 mmas) ~ fp32. TRI: scores skip nt>mt.
// CAUSALK: PV (mt reversed, Ktile=128*(mt+1)).
// EPI 1: fp16 hi/lo split store of alpha*(acc+bias[n])   (PV -> h)
//     2: Ch = rn(acc + bias[m])                           (V proj, BIASM)
//     3: Cf = x + acc + bias[n], unpermuted scatter       (final)
//     4: Ch = rn(acc + bias[n])                           (QK proj)
//     5: Ch = rn(acc)                                     (scores -> S fp16)
template <bool SPLIT, bool TRI, bool CAUSALK, int EPI, bool BIASM>
__global__ __launch_bounds__(256, 2) void mma_fp16_kernel(
    const __half* __restrict__ A0, const __half* __restrict__ A1,
    const __half* __restrict__ B0, const __half* __restrict__ B1,
    float* __restrict__ Cf, __half* __restrict__ Ch, __half* __restrict__ Ch2,
    const float* __restrict__ bias, const float* __restrict__ xres,
    float alpha,
    int lda, int ldb, int ldc, int Kfull,
    long long strA, long long strB, long long strC)
{
    int nt = blockIdx.x, bz = blockIdx.z;
    int mt;
    if (TRI) {
        mt = blockIdx.y;
        if (nt > mt) return;
    } else if (CAUSALK) {
        mt = (int)gridDim.y - 1 - (int)blockIdx.y;
    } else {
        mt = blockIdx.y;
    }
    int Ktile = CAUSALK ? 128 * (mt + 1) : Kfull;

    extern __shared__ uint32_t smw[];
    uint32_t sbase = smem_u32(smw);

    int tid = threadIdx.x;
    int lane = tid & 31, wid = tid >> 5;
    int wm = (wid >> 2) * 64, wn = (wid & 3) * 32;
    int gid = lane >> 2, tg = lane & 3;

    const __half* a0 = A0 + (long long)bz * strA + (long long)mt * 128 * lda;
    const __half* b0 = B0 + (long long)bz * strB + (long long)nt * 128 * ldb;
    const __half* a1 = SPLIT ? A1 + (long long)bz * strA + (long long)mt * 128 * lda : nullptr;
    const __half* b1 = SPLIT ? B1 + (long long)bz * strB + (long long)nt * 128 * ldb : nullptr;

    float acc[4][4][4];
    #pragma unroll
    for (int mi = 0; mi < 4; mi++)
        #pragma unroll
        for (int ni = 0; ni < 4; ni++)
            #pragma unroll
            for (int e = 0; e < 4; e++) acc[mi][ni][e] = 0.f;

    // smem: tiles of 128 rows x 20 uint32 (32 halves + pad) = 10240 B
    const uint32_t TB = 10240u;
    const uint32_t BUF = SPLIT ? 4 * TB : 2 * TB;
    const uint32_t BOFF = SPLIT ? 2 * TB : TB;

    const int NC = Ktile >> 5;

    auto load_chunk = [&](int p, int koff) {
        uint32_t pb = sbase + (uint32_t)p * BUF;
        #pragma unroll
        for (int j = 0; j < 2; j++) {
            int v = tid + j * 256;
            int row = v >> 2, c16 = v & 3;
            uint32_t o = (uint32_t)row * 80u + (uint32_t)c16 * 16u;
            cpa16(pb + o, a0 + (long long)row * lda + koff + c16 * 8);
            cpa16(pb + BOFF + o, b0 + (long long)row * ldb + koff + c16 * 8);
            if (SPLIT) {
                cpa16(pb + TB + o, a1 + (long long)row * lda + koff + c16 * 8);
                cpa16(pb + 3 * TB + o, b1 + (long long)row * ldb + koff + c16 * 8);
            }
        }
    };

    load_chunk(0, 0);
    cpa_commit();
    if (NC > 1) load_chunk(1, 32);
    cpa_commit();

    for (int c = 0; c < NC; c++) {
        cpa_wait1();
        __syncthreads();
        int p = c & 1;
        uint32_t pbw = (uint32_t)p * (BUF >> 2);
        const uint32_t* Ah = smw + pbw;
        const uint32_t* Al = smw + pbw + (TB >> 2);
        const uint32_t* Bh = smw + pbw + (BOFF >> 2);
        const uint32_t* Bl = smw + pbw + 3 * (TB >> 2);

        #pragma unroll
        for (int blk = 0; blk < 2; blk++) {
            int kb = blk * 8 + tg;
            uint32_t ahi[4][4], alo[4][4];
            #pragma unroll
            for (int mi = 0; mi < 4; mi++) {
                int r = wm + mi * 16 + gid;
                ahi[mi][0] = Ah[r * 20 + kb];
                ahi[mi][1] = Ah[(r + 8) * 20 + kb];
                ahi[mi][2] = Ah[r * 20 + kb + 4];
                ahi[mi][3] = Ah[(r + 8) * 20 + kb + 4];
                if (SPLIT) {
                    alo[mi][0] = Al[r * 20 + kb];
                    alo[mi][1] = Al[(r + 8) * 20 + kb];
                    alo[mi][2] = Al[r * 20 + kb + 4];
                    alo[mi][3] = Al[(r + 8) * 20 + kb + 4];
                }
            }
            #pragma unroll
            for (int ni = 0; ni < 4; ni++) {
                int rn = wn + ni * 8 + gid;
                uint32_t bhi[2], blo[2];
                bhi[0] = Bh[rn * 20 + kb];
                bhi[1] = Bh[rn * 20 + kb + 4];
                if (SPLIT) {
                    blo[0] = Bl[rn * 20 + kb];
                    blo[1] = Bl[rn * 20 + kb + 4];
                }
                #pragma unroll
                for (int mi = 0; mi < 4; mi++) {
                    mma16(acc[mi][ni], ahi[mi], bhi);
                    if (SPLIT) {
                        mma16(acc[mi][ni], alo[mi], bhi);
                        mma16(acc[mi][ni], ahi[mi], blo);
                    }
                }
            }
        }
        __syncthreads();
        if (c + 2 < NC) load_chunk(p, (c + 2) * 32);
        cpa_commit();
    }

    // ---------------- epilogue ----------------
    #pragma unroll
    for (int mi = 0; mi < 4; mi++) {
        int r = wm + mi * 16 + gid;
        #pragma unroll
        for (int ni = 0; ni < 4; ni++) {
            int col = wn + ni * 8 + tg * 2;
            #pragma unroll
            for (int half_ = 0; half_ < 2; half_++) {
                int rr = r + half_ * 8;
                float v0 = acc[mi][ni][half_ * 2 + 0];
                float v1 = acc[mi][ni][half_ * 2 + 1];
                if (EPI == 1) {
                    float b0v = bias ? bias[nt * 128 + col]     : 0.f;
                    float b1v = bias ? bias[nt * 128 + col + 1] : 0.f;
                    float w0v = alpha * (v0 + b0v);
                    float w1v = alpha * (v1 + b1v);
                    __half h0 = __float2half_rn(w0v);
                    __half h1 = __float2half_rn(w1v);
                    __half l0 = __float2half_rn(w0v - __half2float(h0));
                    __half l1 = __float2half_rn(w1v - __half2float(h1));
                    long long off = (long long)bz * strC
                                  + (long long)(mt * 128 + rr) * ldc + nt * 128 + col;
                    *(__half2*)(Ch  + off) = __halves2half2(h0, h1);
                    *(__half2*)(Ch2 + off) = __halves2half2(l0, l1);
                } else if (EPI == 2) {
                    float bv = BIASM ? bias[mt * 128 + rr] : 0.f;
                    __half* Cp = Ch + (long long)bz * strC
                               + (long long)(mt * 128 + rr) * ldc + nt * 128 + col;
                    *(__half2*)Cp = __halves2half2(__float2half_rn(v0 + bv),
                                                   __float2half_rn(v1 + bv));
                } else if (EPI == 3) {
                    int m = mt * 128 + rr;
                    int bidx = m >> 12, t = m & 4095;
                    int sidx = ((t & 63) << 6) | (t >> 6);
                    long long i0 = ((long long)bidx << 20)
                                 + ((long long)(nt * 128 + col) << 12) + sidx;
                    long long i1 = i0 + 4096;
                    Cf[i0] = xres[i0] + v0 + bias[nt * 128 + col];
                    Cf[i1] = xres[i1] + v1 + bias[nt * 128 + col + 1];
                } else if (EPI == 4) {
                    float b0v = bias[nt * 128 + col];
                    float b1v = bias[nt * 128 + col + 1];
                    __half* Cp = Ch + (long long)bz * strC
                               + (long long)(mt * 128 + rr) * ldc + nt * 128 + col;
                    *(__half2*)Cp = __halves2half2(__float2half_rn(v0 + b0v),
                                                   __float2half_rn(v1 + b1v));
                } else {  // EPI == 5: plain fp16 store
                    __half* Cp = Ch + (long long)bz * strC
                               + (long long)(mt * 128 + rr) * ldc + nt * 128 + col;
                    *(__half2*)Cp = __halves2half2(__float2half_rn(v0),
                                                   __float2half_rn(v1));
                }
            }
        }
    }
}

// ---------------- masked softmax: fp16 S in, fp16 P out, IN PLACE -------------
__global__ __launch_bounds__(256) void softmax_kernel() {
    int row = blockIdx.x;
    int p = row & 4095;
    int wq = p >> 6;
    int L = (wq + 1) << 6;
    __half* S = g_s + (size_t)row * HWT;
    int tid = threadIdx.x;
    __shared__ float red[8];
    const float NEG = -1e30f;

    float vals[16];
    float mx = NEG;
    #pragma unroll
    for (int it = 0; it < 16; it++) {
        int j = it * 256 + tid;
        float v = (j < L) ? __half2float(S[j]) : NEG;
        vals[it] = v;
        mx = fmaxf(mx, v);
    }
    #pragma unroll
    for (int o = 16; o > 0; o >>= 1)
        mx = fmaxf(mx, __shfl_xor_sync(0xffffffffu, mx, o));
    if ((tid & 31) == 0) red[tid >> 5] = mx;
    __syncthreads();
    mx = red[0];
    #pragma unroll
    for (int i = 1; i < 8; i++) mx = fmaxf(mx, red[i]);
    __syncthreads();

    float sum = 0.f;
    #pragma unroll
    for (int it = 0; it < 16; it++) {
        float e = __expf(vals[it] - mx);
        vals[it] = e;
        sum += e;
    }
    #pragma unroll
    for (int o = 16; o > 0; o >>= 1)
        sum += __shfl_xor_sync(0xffffffffu, sum, o);
    if ((tid & 31) == 0) red[tid >> 5] = sum;
    __syncthreads();
    sum = 0.f;
    #pragma unroll
    for (int i = 0; i < 8; i++) sum += red[i];

    float inv = 1.f / sum;
    #pragma unroll
    for (int it = 0; it < 16; it++) {
        int j = it * 256 + tid;
        if (j < L) S[j] = __float2half_rn(vals[it] * inv);
    }
    if (!(wq & 1) && tid < 64) S[L + tid] = __float2half_rn(0.f);
}

// ---------------- launch ------------------------------------------------------
extern "C" void kernel_launch(void* const* d_in, const int* in_sizes, int n_in,
                              void* d_out, int out_size) {
    (void)in_sizes; (void)n_in; (void)out_size;
    const float* x   = (const float*)d_in[0];
    const float* gnw = (const float*)d_in[1];
    const float* gnb = (const float*)d_in[2];
    const float* w0  = (const float*)d_in[3];
    const float* b0  = (const float*)d_in[4];
    const float* w1  = (const float*)d_in[5];
    const float* b1  = (const float*)d_in[6];
    const float* w2  = (const float*)d_in[7];
    const float* b2  = (const float*)d_in[8];
    const float* w3  = (const float*)d_in[9];
    const float* b3  = (const float*)d_in[10];
    float* out = (float*)d_out;

    const int SM_SPLIT  = 81920;   // split: 4 tiles x2 buffers
    const int SM_SINGLE = 40960;   // single: 2 tiles x2 buffers
    cudaFuncSetAttribute(mma_fp16_kernel<false, false, false, 4, false>,
                         cudaFuncAttributeMaxDynamicSharedMemorySize, SM_SINGLE);
    cudaFuncSetAttribute(mma_fp16_kernel<false, false, false, 2, true>,
                         cudaFuncAttributeMaxDynamicSharedMemorySize, SM_SINGLE);
    cudaFuncSetAttribute(mma_fp16_kernel<false, true, false, 5, false>,
                         cudaFuncAttributeMaxDynamicSharedMemorySize, SM_SINGLE);
    cudaFuncSetAttribute(mma_fp16_kernel<false, false, true, 1, false>,
                         cudaFuncAttributeMaxDynamicSharedMemorySize, SM_SINGLE);
    cudaFuncSetAttribute(mma_fp16_kernel<true, false, false, 3, false>,
                         cudaFuncAttributeMaxDynamicSharedMemorySize, SM_SPLIT);

    void *p0, *p1, *p2, *p3, *p4, *p5, *p6, *p7, *p8, *p9;
    cudaGetSymbolAddress(&p0, g_hn);
    cudaGetSymbolAddress(&p1, g_qk);
    cudaGetSymbolAddress(&p2, g_vt);
    cudaGetSymbolAddress(&p3, g_h_hi);
    cudaGetSymbolAddress(&p4, g_h_lo);
    cudaGetSymbolAddress(&p5, g_wqk);
    cudaGetSymbolAddress(&p6, g_w2t);
    cudaGetSymbolAddress(&p7, g_w3hi);
    cudaGetSymbolAddress(&p8, g_w3lo);
    cudaGetSymbolAddress(&p9, g_s);
    __half* hn  = (__half*)p0;
    __half* qk  = (__half*)p1;
    __half* vt  = (__half*)p2;
    __half* hh  = (__half*)p3;  __half* hl = (__half*)p4;
    __half* wqk = (__half*)p5;
    __half* w2t = (__half*)p6;
    __half* w3h = (__half*)p7;  __half* w3l = (__half*)p8;
    __half* s   = (__half*)p9;

    void* pb;
    cudaGetSymbolAddress(&pb, g_bqk);
    float* bqk = (float*)pb;

    const long long HN_STR = (long long)HWT * CCH;       // 1,048,576
    const long long QK_STR = (long long)HWT * 2 * CCH;   // 2,097,152
    const long long S_STR  = (long long)HWT * HWT;       // 16,777,216

    // 1. GroupNorm (permuted, fp16)
    groupnorm_kernel<<<512, 256>>>(x, gnw, gnb);

    // 2. weight prep: transposes + fp16 (+w3 split) + bias concat
    wprep_all<<<256, dim3(32, 32)>>>(w0, b0, w1, b1, w2, w3);

    // 3. Fused Q|K projection -> g_qk [tok][512] (w0,b0 pre-scaled by 1/16)
    dim3 gqk(4, 128, 1);
    mma_fp16_kernel<false, false, false, 4, false><<<gqk, 256, SM_SINGLE>>>(
        hn, nullptr, wqk, nullptr, nullptr, qk, nullptr, bqk, nullptr,
        1.0f, CCH, CCH, 2 * CCH, CCH, 0, 0, 0);

    // 4. V projection, transposed out: vt[c][p] = W2^T x HN^T + b2
    dim3 gv(32, 2, 4);
    mma_fp16_kernel<false, false, false, 2, true><<<gv, 256, SM_SINGLE>>>(
        w2t, nullptr, hn, nullptr, nullptr, vt, nullptr, b2, nullptr,
        1.0f, CCH, CCH, HWT, CCH, 0, HN_STR, HN_STR);

    // 5. Scores S = Q*K^T (single fp16, triangular tiles, fp16 store)
    dim3 gs(32, 32, 4);
    mma_fp16_kernel<false, true, false, 5, false><<<gs, 256, SM_SINGLE>>>(
        qk, nullptr, qk + CCH, nullptr, nullptr, s, nullptr, nullptr, nullptr,
        1.0f, 2 * CCH, 2 * CCH, HWT, CCH, QK_STR, QK_STR, S_STR);

    // 6. Softmax (fp16 in/out, in place, pad zero-fill)
    softmax_kernel<<<NTOK, 256>>>();

    // 7. H = P * V^T (single fp16, causal K range; fp16 split output)
    dim3 gp(2, 32, 4);
    mma_fp16_kernel<false, false, true, 1, false><<<gp, 256, SM_SINGLE>>>(
        s, nullptr, vt, nullptr, nullptr, hh, hl, nullptr, nullptr,
        1.0f, HWT, HWT, CCH, 0, S_STR, HN_STR, HN_STR);

    // 8. out = x + H*w3 + b3 (split 3-mma, scatter + unpermute)
    dim3 gf(2, 128, 1);
    mma_fp16_kernel<true, false, false, 3, false><<<gf, 256, SM_SPLIT>>>(
        hh, hl, w3h, w3l, out, nullptr, nullptr, b3, x,
        1.0f, CCH, CCH, 0, CCH, 0, 0, 0);
}

// round 10
// speedup vs baseline: 3.6790x; 1.2347x over previous
#include <cuda_runtime.h>
#include <cuda_fp16.h>
#include <math.h>
#include <stdint.h>

// Problem dims
#define BCH 4
#define CCH 256
#define HWT 4096          // H*W = 64*64
#define NTOK 16384        // B*HW

// Token order inside each batch is PERMUTED: p = w*64 + h. Causal mask becomes
// block-lower-triangular at 64-token granularity, diagonal fully allowed.

// ---------------- scratch ------------------------------------------------------
__device__ __align__(256) __half g_hn  [(size_t)NTOK * CCH];         // fp16 single
__device__ __align__(256) __half g_qk  [(size_t)NTOK * 2 * CCH];     // [tok][512]: Q|K
__device__ __align__(256) __half g_vt  [(size_t)NTOK * CCH];         // [b][c][p]
__device__ __align__(256) __half g_h_hi[(size_t)NTOK * CCH];
__device__ __align__(256) __half g_h_lo[(size_t)NTOK * CCH];
__device__ __align__(256) __half g_wqk [2 * CCH * CCH];              // [512][256] w0t/16 | w1t
__device__ __align__(256) __half g_w2t [CCH * CCH];
__device__ __align__(256) __half g_w3hi[CCH * CCH];
__device__ __align__(256) __half g_w3lo[CCH * CCH];
__device__ __align__(256) float  g_bqk [2 * CCH];                    // b0/16 | b1
__device__ __align__(256) __half g_s   [(size_t)BCH * HWT * HWT];    // S then P (in place)

// ---------------- helpers -----------------------------------------------------
__device__ __forceinline__ uint32_t smem_u32(const void* p) {
    uint32_t a;
    asm("{ .reg .u64 t; cvta.to.shared.u64 t, %1; cvt.u32.u64 %0, t; }"
        : "=r"(a) : "l"(p));
    return a;
}
__device__ __forceinline__ void cpa16(uint32_t dst, const void* src) {
    asm volatile("cp.async.cg.shared.global [%0], [%1], 16;"
                 :: "r"(dst), "l"(src));
}
__device__ __forceinline__ void cpa_commit() {
    asm volatile("cp.async.commit_group;" ::: "memory");
}
__device__ __forceinline__ void cpa_wait1() {
    asm volatile("cp.async.wait_group 1;" ::: "memory");
}
// m16n8k16 fp16 MMA, fp32 accumulate
__device__ __forceinline__ void mma16(float* c, const uint32_t* a, const uint32_t* b) {
    asm volatile("mma.sync.aligned.m16n8k16.row.col.f32.f16.f16.f32 "
        "{%0,%1,%2,%3}, {%4,%5,%6,%7}, {%8,%9}, {%0,%1,%2,%3};"
        : "+f"(c[0]), "+f"(c[1]), "+f"(c[2]), "+f"(c[3])
        : "r"(a[0]), "r"(a[1]), "r"(a[2]), "r"(a[3]), "r"(b[0]), "r"(b[1]));
}
__device__ __forceinline__ void ldm_x4(uint32_t* r, uint32_t addr) {
    asm volatile("ldmatrix.sync.aligned.m8n8.x4.shared.b16 {%0,%1,%2,%3}, [%4];"
        : "=r"(r[0]), "=r"(r[1]), "=r"(r[2]), "=r"(r[3]) : "r"(addr));
}

// ---------------- GroupNorm -> permuted hn (fp16 single) ----------------------
__global__ __launch_bounds__(256) void groupnorm_kernel(
    const float* __restrict__ x,
    const float* __restrict__ gnw,
    const float* __restrict__ gnb)
{
    __shared__ float tile[CCH][33];
    __shared__ float sw[CCH];
    __shared__ float sb[CCH];
    int tid = threadIdx.x;
    int b = blockIdx.x >> 7;
    int hwbase = (blockIdx.x & 127) << 5;
    int tx = tid & 31, ty = tid >> 5;

    const float* xb = x + (size_t)b * CCH * HWT;
    for (int c = ty; c < CCH; c += 8)
        tile[c][tx] = xb[(size_t)c * HWT + hwbase + tx];
    sw[tid] = gnw[tid];
    sb[tid] = gnb[tid];
    __syncthreads();

    int tok = tx;
    #pragma unroll
    for (int gi = 0; gi < 4; gi++) {
        int c0 = (ty + gi * 8) * 8;
        float s = 0.f, ss = 0.f;
        #pragma unroll
        for (int j = 0; j < 8; j++) {
            float v = tile[c0 + j][tok];
            s += v; ss += v * v;
        }
        float m   = s * 0.125f;
        float var = ss * 0.125f - m * m;
        float r   = rsqrtf(var + 1e-6f);
        #pragma unroll
        for (int j = 0; j < 8; j++) {
            int c = c0 + j;
            tile[c][tok] = (tile[c][tok] - m) * r * sw[c] + sb[c];
        }
    }
    __syncthreads();

    int h = hwbase >> 6;
    __half* hh = g_hn + ((size_t)b << 12) * CCH;
    for (int it = 0; it < 32; it++) {
        int w = (hwbase + it) & 63;
        int p = (w << 6) | h;
        hh[(size_t)p * CCH + tid] = __float2half_rn(tile[tid][it]);
    }
}

// ---------------- weight prep: all 4 transposes + bias concat -----------------
__global__ void wprep_all(const float* __restrict__ w0, const float* __restrict__ b0,
                          const float* __restrict__ w1, const float* __restrict__ b1,
                          const float* __restrict__ w2, const float* __restrict__ w3)
{
    __shared__ float t[32][33];
    int bid = blockIdx.x;            // 0..255
    int mat = bid >> 6;
    int tile_ = bid & 63;
    int bx = (tile_ & 7) * 32, by = (tile_ >> 3) * 32;
    int tx = threadIdx.x, ty = threadIdx.y;

    const float* w = (mat == 0) ? w0 : (mat == 1) ? w1 : (mat == 2) ? w2 : w3;
    t[ty][tx] = w[(by + ty) * CCH + bx + tx];
    __syncthreads();
    float v = t[tx][ty];
    int dst = (bx + ty) * CCH + by + tx;
    if (mat == 0) {
        g_wqk[dst] = __float2half_rn(v * 0.0625f);
    } else if (mat == 1) {
        g_wqk[CCH * CCH + dst] = __float2half_rn(v);
    } else if (mat == 2) {
        g_w2t[dst] = __float2half_rn(v);
    } else {
        __half hi = __float2half_rn(v);
        g_w3hi[dst] = hi;
        g_w3lo[dst] = __float2half_rn(v - __half2float(hi));
    }
    if (bid == 0) {
        int t0 = ty * 32 + tx;
        if (t0 < 256)      g_bqk[t0] = b0[t0] * 0.0625f;
        else if (t0 < 512) g_bqk[t0] = b1[t0 - 256];
    }
}

// ---------------- unified fp16 tensor-core NT GEMM (ldmatrix, k64) ------------
// C[128x128] tiles; A [M][K] rm, B [N][K] rm, fp16, XOR-swizzled smem.
// SPLIT: 2-term hi/lo (3 mmas) ~ fp32. TRI: scores skip nt>mt.
// CAUSALK: PV (mt reversed, Ktile=128*(mt+1)).
// EPI 1: fp16 hi/lo split store of alpha*(acc+bias[n])   (PV -> h)
//     2: Ch = rn(acc + bias[m])                           (V proj, BIASM)
//     3: Cf = x + acc + bias[n], unpermuted scatter       (final)
//     4: Ch = rn(acc + bias[n])                           (QK proj)
//     5: Ch = rn(acc)                                     (scores -> S fp16)
template <bool SPLIT, bool TRI, bool CAUSALK, int EPI, bool BIASM>
__global__ __launch_bounds__(256, SPLIT ? 1 : 2) void mma_fp16_kernel(
    const __half* __restrict__ A0, const __half* __restrict__ A1,
    const __half* __restrict__ B0, const __half* __restrict__ B1,
    float* __restrict__ Cf, __half* __restrict__ Ch, __half* __restrict__ Ch2,
    const float* __restrict__ bias, const float* __restrict__ xres,
    float alpha,
    int lda, int ldb, int ldc, int Kfull,
    long long strA, long long strB, long long strC)
{
    int nt = blockIdx.x, bz = blockIdx.z;
    int mt;
    if (TRI) {
        mt = blockIdx.y;
        if (nt > mt) return;
    } else if (CAUSALK) {
        mt = (int)gridDim.y - 1 - (int)blockIdx.y;
    } else {
        mt = blockIdx.y;
    }
    int Ktile = CAUSALK ? 128 * (mt + 1) : Kfull;

    extern __shared__ uint32_t smw[];
    uint32_t sbase = smem_u32(smw);

    int tid = threadIdx.x;
    int lane = tid & 31, wid = tid >> 5;
    int wm = (wid >> 2) * 64, wn = (wid & 3) * 32;
    int gid = lane >> 2, tg = lane & 3;
    int l8 = lane & 7, quad = lane >> 3;

    const __half* a0 = A0 + (long long)bz * strA + (long long)mt * 128 * lda;
    const __half* b0 = B0 + (long long)bz * strB + (long long)nt * 128 * ldb;
    const __half* a1 = SPLIT ? A1 + (long long)bz * strA + (long long)mt * 128 * lda : nullptr;
    const __half* b1 = SPLIT ? B1 + (long long)bz * strB + (long long)nt * 128 * ldb : nullptr;

    float acc[4][4][4];
    #pragma unroll
    for (int mi = 0; mi < 4; mi++)
        #pragma unroll
        for (int ni = 0; ni < 4; ni++)
            #pragma unroll
            for (int e = 0; e < 4; e++) acc[mi][ni][e] = 0.f;

    // tiles: 128 rows x 64 halves (128B rows), XOR swizzle within row = 16 KB
    const uint32_t TB = 16384u;
    const uint32_t NT_ = SPLIT ? 4u : 2u;     // tiles per buffer (A[,Al],B[,Bl])
    const uint32_t BUF = NT_ * TB;

    const int NC = Ktile >> 6;   // k-chunk 64

    // cp.async loader: one tile = 128 rows x 8 x 16B = 1024 transfers
    auto load_tile = [&](uint32_t dstbase, const __half* src, int ld, int koff) {
        #pragma unroll
        for (int j = 0; j < 4; j++) {
            int v = tid + j * 256;
            int row = v >> 3, c16 = v & 7;
            uint32_t dst = dstbase + (uint32_t)row * 128u
                         + (((uint32_t)c16 * 16u) ^ ((uint32_t)(row & 7) << 4));
            cpa16(dst, src + (long long)row * ld + koff + c16 * 8);
        }
    };
    auto load_chunk = [&](int p, int koff) {
        uint32_t pb = sbase + (uint32_t)p * BUF;
        load_tile(pb, a0, lda, koff);
        load_tile(pb + (SPLIT ? 2u : 1u) * TB, b0, ldb, koff);
        if (SPLIT) {
            load_tile(pb + TB, a1, lda, koff);
            load_tile(pb + 3u * TB, b1, ldb, koff);
        }
    };

    load_chunk(0, 0);
    cpa_commit();
    if (NC > 1) load_chunk(1, 64);
    cpa_commit();

    // per-lane ldmatrix address components (swizzle term = l8<<4, row&7 == l8)
    uint32_t a_row = (uint32_t)(wm + (quad & 1) * 8 + l8) * 128u;
    uint32_t a_cq  = (uint32_t)(quad >> 1) * 16u;
    uint32_t b_cq  = (uint32_t)(quad & 1) * 16u;
    uint32_t swl   = (uint32_t)l8 << 4;
    uint32_t b_row0 = (uint32_t)(wn + (0 + (quad >> 1)) * 8 + l8) * 128u;
    uint32_t b_row1 = (uint32_t)(wn + (2 + (quad >> 1)) * 8 + l8) * 128u;

    for (int c = 0; c < NC; c++) {
        cpa_wait1();
        __syncthreads();
        int p = c & 1;
        uint32_t Ab = sbase + (uint32_t)p * BUF;
        uint32_t Bb = Ab + (SPLIT ? 2u : 1u) * TB;

        #pragma unroll
        for (int kb = 0; kb < 4; kb++) {
            uint32_t acol = ((uint32_t)kb * 32u + a_cq) ^ swl;
            uint32_t bcol = ((uint32_t)kb * 32u + b_cq) ^ swl;
            uint32_t af[4][4], bf[2][4];
            #pragma unroll
            for (int mi = 0; mi < 4; mi++)
                ldm_x4(af[mi], Ab + a_row + (uint32_t)mi * 2048u + acol);
            ldm_x4(bf[0], Bb + b_row0 + bcol);
            ldm_x4(bf[1], Bb + b_row1 + bcol);

            #pragma unroll
            for (int ni = 0; ni < 4; ni++) {
                const uint32_t* bp = &bf[ni >> 1][(ni & 1) * 2];
                #pragma unroll
                for (int mi = 0; mi < 4; mi++)
                    mma16(acc[mi][ni], af[mi], bp);
            }
            if (SPLIT) {
                uint32_t afl[4][4], bfl[2][4];
                #pragma unroll
                for (int mi = 0; mi < 4; mi++)
                    ldm_x4(afl[mi], Ab + TB + a_row + (uint32_t)mi * 2048u + acol);
                ldm_x4(bfl[0], Bb + TB + b_row0 + bcol);
                ldm_x4(bfl[1], Bb + TB + b_row1 + bcol);
                #pragma unroll
                for (int ni = 0; ni < 4; ni++) {
                    const uint32_t* bph = &bf[ni >> 1][(ni & 1) * 2];
                    const uint32_t* bpl = &bfl[ni >> 1][(ni & 1) * 2];
                    #pragma unroll
                    for (int mi = 0; mi < 4; mi++) {
                        mma16(acc[mi][ni], afl[mi], bph);
                        mma16(acc[mi][ni], af[mi], bpl);
                    }
                }
            }
        }
        __syncthreads();
        if (c + 2 < NC) load_chunk(p, (c + 2) * 64);
        cpa_commit();
    }

    // ---------------- epilogue ----------------
    #pragma unroll
    for (int mi = 0; mi < 4; mi++) {
        int r = wm + mi * 16 + gid;
        #pragma unroll
        for (int ni = 0; ni < 4; ni++) {
            int col = wn + ni * 8 + tg * 2;
            #pragma unroll
            for (int half_ = 0; half_ < 2; half_++) {
                int rr = r + half_ * 8;
                float v0 = acc[mi][ni][half_ * 2 + 0];
                float v1 = acc[mi][ni][half_ * 2 + 1];
                if (EPI == 1) {
                    float b0v = bias ? bias[nt * 128 + col]     : 0.f;
                    float b1v = bias ? bias[nt * 128 + col + 1] : 0.f;
                    float w0v = alpha * (v0 + b0v);
                    float w1v = alpha * (v1 + b1v);
                    __half h0 = __float2half_rn(w0v);
                    __half h1 = __float2half_rn(w1v);
                    __half l0 = __float2half_rn(w0v - __half2float(h0));
                    __half l1 = __float2half_rn(w1v - __half2float(h1));
                    long long off = (long long)bz * strC
                                  + (long long)(mt * 128 + rr) * ldc + nt * 128 + col;
                    *(__half2*)(Ch  + off) = __halves2half2(h0, h1);
                    *(__half2*)(Ch2 + off) = __halves2half2(l0, l1);
                } else if (EPI == 2) {
                    float bv = BIASM ? bias[mt * 128 + rr] : 0.f;
                    __half* Cp = Ch + (long long)bz * strC
                               + (long long)(mt * 128 + rr) * ldc + nt * 128 + col;
                    *(__half2*)Cp = __halves2half2(__float2half_rn(v0 + bv),
                                                   __float2half_rn(v1 + bv));
                } else if (EPI == 3) {
                    int m = mt * 128 + rr;
                    int bidx = m >> 12, t = m & 4095;
                    int sidx = ((t & 63) << 6) | (t >> 6);
                    long long i0 = ((long long)bidx << 20)
                                 + ((long long)(nt * 128 + col) << 12) + sidx;
                    long long i1 = i0 + 4096;
                    Cf[i0] = xres[i0] + v0 + bias[nt * 128 + col];
                    Cf[i1] = xres[i1] + v1 + bias[nt * 128 + col + 1];
                } else if (EPI == 4) {
                    float b0v = bias[nt * 128 + col];
                    float b1v = bias[nt * 128 + col + 1];
                    __half* Cp = Ch + (long long)bz * strC
                               + (long long)(mt * 128 + rr) * ldc + nt * 128 + col;
                    *(__half2*)Cp = __halves2half2(__float2half_rn(v0 + b0v),
                                                   __float2half_rn(v1 + b1v));
                } else {  // EPI == 5
                    __half* Cp = Ch + (long long)bz * strC
                               + (long long)(mt * 128 + rr) * ldc + nt * 128 + col;
                    *(__half2*)Cp = __halves2half2(__float2half_rn(v0),
                                                   __float2half_rn(v1));
                }
            }
        }
    }
}

// ---------------- masked softmax: fp16 in/out, in place, half2 ---------------
__global__ __launch_bounds__(256) void softmax_kernel() {
    int row = blockIdx.x;
    int p = row & 4095;
    int wq = p >> 6;
    int L = (wq + 1) << 6;
    __half2* S2 = (__half2*)(g_s + (size_t)row * HWT);
    int L2 = L >> 1;
    int tid = threadIdx.x;
    __shared__ float red[8];
    const float NEG = -1e30f;

    float2 vals[8];
    float mx = NEG;
    #pragma unroll
    for (int it = 0; it < 8; it++) {
        int j = it * 256 + tid;
        float2 v = (j < L2) ? __half22float2(S2[j]) : make_float2(NEG, NEG);
        vals[it] = v;
        mx = fmaxf(mx, fmaxf(v.x, v.y));
    }
    #pragma unroll
    for (int o = 16; o > 0; o >>= 1)
        mx = fmaxf(mx, __shfl_xor_sync(0xffffffffu, mx, o));
    if ((tid & 31) == 0) red[tid >> 5] = mx;
    __syncthreads();
    mx = red[0];
    #pragma unroll
    for (int i = 1; i < 8; i++) mx = fmaxf(mx, red[i]);
    __syncthreads();

    float sum = 0.f;
    #pragma unroll
    for (int it = 0; it < 8; it++) {
        float e0 = __expf(vals[it].x - mx);
        float e1 = __expf(vals[it].y - mx);
        vals[it] = make_float2(e0, e1);
        sum += e0 + e1;
    }
    #pragma unroll
    for (int o = 16; o > 0; o >>= 1)
        sum += __shfl_xor_sync(0xffffffffu, sum, o);
    if ((tid & 31) == 0) red[tid >> 5] = sum;
    __syncthreads();
    sum = 0.f;
    #pragma unroll
    for (int i = 0; i < 8; i++) sum += red[i];

    float inv = 1.f / sum;
    #pragma unroll
    for (int it = 0; it < 8; it++) {
        int j = it * 256 + tid;
        if (j < L2)
            S2[j] = __floats2half2_rn(vals[it].x * inv, vals[it].y * inv);
    }
    if (!(wq & 1) && tid < 32)
        S2[L2 + tid] = __floats2half2_rn(0.f, 0.f);
}

// ---------------- launch ------------------------------------------------------
extern "C" void kernel_launch(void* const* d_in, const int* in_sizes, int n_in,
                              void* d_out, int out_size) {
    (void)in_sizes; (void)n_in; (void)out_size;
    const float* x   = (const float*)d_in[0];
    const float* gnw = (const float*)d_in[1];
    const float* gnb = (const float*)d_in[2];
    const float* w0  = (const float*)d_in[3];
    const float* b0  = (const float*)d_in[4];
    const float* w1  = (const float*)d_in[5];
    const float* b1  = (const float*)d_in[6];
    const float* w2  = (const float*)d_in[7];
    const float* b2  = (const float*)d_in[8];
    const float* w3  = (const float*)d_in[9];
    const float* b3  = (const float*)d_in[10];
    float* out = (float*)d_out;

    const int SM_SPLIT  = 131072;  // 4 tiles x 16KB x 2 buffers
    const int SM_SINGLE = 65536;   // 2 tiles x 16KB x 2 buffers
    cudaFuncSetAttribute(mma_fp16_kernel<false, false, false, 4, false>,
                         cudaFuncAttributeMaxDynamicSharedMemorySize, SM_SINGLE);
    cudaFuncSetAttribute(mma_fp16_kernel<false, false, false, 2, true>,
                         cudaFuncAttributeMaxDynamicSharedMemorySize, SM_SINGLE);
    cudaFuncSetAttribute(mma_fp16_kernel<false, true, false, 5, false>,
                         cudaFuncAttributeMaxDynamicSharedMemorySize, SM_SINGLE);
    cudaFuncSetAttribute(mma_fp16_kernel<false, false, true, 1, false>,
                         cudaFuncAttributeMaxDynamicSharedMemorySize, SM_SINGLE);
    cudaFuncSetAttribute(mma_fp16_kernel<true, false, false, 3, false>,
                         cudaFuncAttributeMaxDynamicSharedMemorySize, SM_SPLIT);

    void *p0, *p1, *p2, *p3, *p4, *p5, *p6, *p7, *p8, *p9;
    cudaGetSymbolAddress(&p0, g_hn);
    cudaGetSymbolAddress(&p1, g_qk);
    cudaGetSymbolAddress(&p2, g_vt);
    cudaGetSymbolAddress(&p3, g_h_hi);
    cudaGetSymbolAddress(&p4, g_h_lo);
    cudaGetSymbolAddress(&p5, g_wqk);
    cudaGetSymbolAddress(&p6, g_w2t);
    cudaGetSymbolAddress(&p7, g_w3hi);
    cudaGetSymbolAddress(&p8, g_w3lo);
    cudaGetSymbolAddress(&p9, g_s);
    __half* hn  = (__half*)p0;
    __half* qk  = (__half*)p1;
    __half* vt  = (__half*)p2;
    __half* hh  = (__half*)p3;  __half* hl = (__half*)p4;
    __half* wqk = (__half*)p5;
    __half* w2t = (__half*)p6;
    __half* w3h = (__half*)p7;  __half* w3l = (__half*)p8;
    __half* s   = (__half*)p9;

    void* pb;
    cudaGetSymbolAddress(&pb, g_bqk);
    float* bqk = (float*)pb;

    const long long HN_STR = (long long)HWT * CCH;       // 1,048,576
    const long long QK_STR = (long long)HWT * 2 * CCH;   // 2,097,152
    const long long S_STR  = (long long)HWT * HWT;       // 16,777,216

    // 1. GroupNorm (permuted, fp16)
    groupnorm_kernel<<<512, 256>>>(x, gnw, gnb);

    // 2. weight prep
    wprep_all<<<256, dim3(32, 32)>>>(w0, b0, w1, b1, w2, w3);

    // 3. Fused Q|K projection -> g_qk [tok][512]
    dim3 gqk(4, 128, 1);
    mma_fp16_kernel<false, false, false, 4, false><<<gqk, 256, SM_SINGLE>>>(
        hn, nullptr, wqk, nullptr, nullptr, qk, nullptr, bqk, nullptr,
        1.0f, CCH, CCH, 2 * CCH, CCH, 0, 0, 0);

    // 4. V projection, transposed out: vt[c][p] = W2^T x HN^T + b2
    dim3 gv(32, 2, 4);
    mma_fp16_kernel<false, false, false, 2, true><<<gv, 256, SM_SINGLE>>>(
        w2t, nullptr, hn, nullptr, nullptr, vt, nullptr, b2, nullptr,
        1.0f, CCH, CCH, HWT, CCH, 0, HN_STR, HN_STR);

    // 5. Scores S = Q*K^T (triangular tiles, fp16 store)
    dim3 gs(32, 32, 4);
    mma_fp16_kernel<false, true, false, 5, false><<<gs, 256, SM_SINGLE>>>(
        qk, nullptr, qk + CCH, nullptr, nullptr, s, nullptr, nullptr, nullptr,
        1.0f, 2 * CCH, 2 * CCH, HWT, CCH, QK_STR, QK_STR, S_STR);

    // 6. Softmax (fp16 in/out, in place)
    softmax_kernel<<<NTOK, 256>>>();

    // 7. H = P * V^T (causal K range; fp16 split output)
    dim3 gp(2, 32, 4);
    mma_fp16_kernel<false, false, true, 1, false><<<gp, 256, SM_SINGLE>>>(
        s, nullptr, vt, nullptr, nullptr, hh, hl, nullptr, nullptr,
        1.0f, HWT, HWT, CCH, 0, S_STR, HN_STR, HN_STR);

    // 8. out = x + H*w3 + b3 (split 3-mma, scatter + unpermute)
    dim3 gf(2, 128, 1);
    mma_fp16_kernel<true, false, false, 3, false><<<gf, 256, SM_SPLIT>>>(
        hh, hl, w3h, w3l, out, nullptr, nullptr, b3, x,
        1.0f, CCH, CCH, 0, CCH, 0, 0, 0);
}

// round 13
// speedup vs baseline: 3.6952x; 1.0044x over previous
#include <cuda_runtime.h>
#include <cuda_fp16.h>
#include <math.h>
#include <stdint.h>

// Problem dims
#define BCH 4
#define CCH 256
#define HWT 4096          // H*W = 64*64
#define NTOK 16384        // B*HW

// Token order inside each batch is PERMUTED: p = w*64 + h. Causal mask becomes
// block-lower-triangular at 64-token granularity, diagonal fully allowed.

// ---------------- scratch ------------------------------------------------------
__device__ __align__(256) __half g_hn  [(size_t)NTOK * CCH];         // fp16
__device__ __align__(256) __half g_qk  [(size_t)NTOK * 2 * CCH];     // [tok][512]: Q|K
__device__ __align__(256) __half g_vt  [(size_t)NTOK * CCH];         // [b][c][p]
__device__ __align__(256) __half g_h_p0[(size_t)NTOK * CCH];         // PV K-partial 0
__device__ __align__(256) __half g_h_p1[(size_t)NTOK * CCH];         // PV K-partial 1
__device__ __align__(256) __half g_wqk [2 * CCH * CCH];              // [512][256] w0t/16 | w1t
__device__ __align__(256) __half g_w2t [CCH * CCH];
__device__ __align__(256) __half g_w3hi[CCH * CCH];
__device__ __align__(256) __half g_w3lo[CCH * CCH];
__device__ __align__(256) float  g_bqk [2 * CCH];                    // b0/16 | b1
__device__ __align__(256) __half g_s   [(size_t)BCH * HWT * HWT];    // S then P (in place)

// ---------------- helpers -----------------------------------------------------
__device__ __forceinline__ uint32_t smem_u32(const void* p) {
    uint32_t a;
    asm("{ .reg .u64 t; cvta.to.shared.u64 t, %1; cvt.u32.u64 %0, t; }"
        : "=r"(a) : "l"(p));
    return a;
}
__device__ __forceinline__ void cpa16(uint32_t dst, const void* src) {
    asm volatile("cp.async.cg.shared.global [%0], [%1], 16;"
                 :: "r"(dst), "l"(src));
}
__device__ __forceinline__ void cpa_commit() {
    asm volatile("cp.async.commit_group;" ::: "memory");
}
__device__ __forceinline__ void cpa_wait2() {
    asm volatile("cp.async.wait_group 2;" ::: "memory");
}
__device__ __forceinline__ void mma16(float* c, const uint32_t* a, const uint32_t* b) {
    asm volatile("mma.sync.aligned.m16n8k16.row.col.f32.f16.f16.f32 "
        "{%0,%1,%2,%3}, {%4,%5,%6,%7}, {%8,%9}, {%0,%1,%2,%3};"
        : "+f"(c[0]), "+f"(c[1]), "+f"(c[2]), "+f"(c[3])
        : "r"(a[0]), "r"(a[1]), "r"(a[2]), "r"(a[3]), "r"(b[0]), "r"(b[1]));
}
__device__ __forceinline__ void ldm_x4(uint32_t* r, uint32_t addr) {
    asm volatile("ldmatrix.sync.aligned.m8n8.x4.shared.b16 {%0,%1,%2,%3}, [%4];"
        : "=r"(r[0]), "=r"(r[1]), "=r"(r[2]), "=r"(r[3]) : "r"(addr));
}
__device__ __forceinline__ uint32_t hadd2_u32(uint32_t a, uint32_t b) {
    __half2 r = __hadd2(*(__half2*)&a, *(__half2*)&b);
    return *(uint32_t*)&r;
}

// ---------------- GroupNorm -> permuted hn (fp16) -----------------------------
__global__ __launch_bounds__(256) void groupnorm_kernel(
    const float* __restrict__ x,
    const float* __restrict__ gnw,
    const float* __restrict__ gnb)
{
    __shared__ float tile[CCH][33];
    __shared__ float sw[CCH];
    __shared__ float sb[CCH];
    int tid = threadIdx.x;
    int b = blockIdx.x >> 7;
    int hwbase = (blockIdx.x & 127) << 5;
    int tx = tid & 31, ty = tid >> 5;

    const float* xb = x + (size_t)b * CCH * HWT;
    for (int c = ty; c < CCH; c += 8)
        tile[c][tx] = xb[(size_t)c * HWT + hwbase + tx];
    sw[tid] = gnw[tid];
    sb[tid] = gnb[tid];
    __syncthreads();

    int tok = tx;
    #pragma unroll
    for (int gi = 0; gi < 4; gi++) {
        int c0 = (ty + gi * 8) * 8;
        float s = 0.f, ss = 0.f;
        #pragma unroll
        for (int j = 0; j < 8; j++) {
            float v = tile[c0 + j][tok];
            s += v; ss += v * v;
        }
        float m   = s * 0.125f;
        float var = ss * 0.125f - m * m;
        float r   = rsqrtf(var + 1e-6f);
        #pragma unroll
        for (int j = 0; j < 8; j++) {
            int c = c0 + j;
            tile[c][tok] = (tile[c][tok] - m) * r * sw[c] + sb[c];
        }
    }
    __syncthreads();

    int h = hwbase >> 6;
    __half* hh = g_hn + ((size_t)b << 12) * CCH;
    for (int it = 0; it < 32; it++) {
        int w = (hwbase + it) & 63;
        int p = (w << 6) | h;
        hh[(size_t)p * CCH + tid] = __float2half_rn(tile[tid][it]);
    }
}

// ---------------- weight prep -------------------------------------------------
__global__ void wprep_all(const float* __restrict__ w0, const float* __restrict__ b0,
                          const float* __restrict__ w1, const float* __restrict__ b1,
                          const float* __restrict__ w2, const float* __restrict__ w3)
{
    __shared__ float t[32][33];
    int bid = blockIdx.x;
    int mat = bid >> 6;
    int tile_ = bid & 63;
    int bx = (tile_ & 7) * 32, by = (tile_ >> 3) * 32;
    int tx = threadIdx.x, ty = threadIdx.y;

    const float* w = (mat == 0) ? w0 : (mat == 1) ? w1 : (mat == 2) ? w2 : w3;
    t[ty][tx] = w[(by + ty) * CCH + bx + tx];
    __syncthreads();
    float v = t[tx][ty];
    int dst = (bx + ty) * CCH + by + tx;
    if (mat == 0) {
        g_wqk[dst] = __float2half_rn(v * 0.0625f);
    } else if (mat == 1) {
        g_wqk[CCH * CCH + dst] = __float2half_rn(v);
    } else if (mat == 2) {
        g_w2t[dst] = __float2half_rn(v);
    } else {
        __half hi = __float2half_rn(v);
        g_w3hi[dst] = hi;
        g_w3lo[dst] = __float2half_rn(v - __half2float(hi));
    }
    if (bid == 0) {
        int t0 = ty * 32 + tx;
        if (t0 < 256)      g_bqk[t0] = b0[t0] * 0.0625f;
        else if (t0 < 512) g_bqk[t0] = b1[t0 - 256];
    }
}

// ---------------- unified fp16 tensor-core NT GEMM (3-stage, ldmatrix) --------
// C[128x128] tiles; A [M][K] rm, B [N][K] rm, fp16, XOR-swizzled smem.
// MODE 0: single (A,B). MODE 2: A = A0+A1 (fragment hadd2), B = B0+B1 split
//         (2 mmas) — used for final proj with PV partials x w3 hi/lo.
// TRI: scores skip nt>mt. CAUSALK: PV K-split (y -> mt desc, seg 0/1,
//      Ktile=(mt+1)*64 per seg).
// EPI 1: partial fp16 store -> (seg? Ch2 : Ch)           (PV)
//     2: Ch = rn(acc + bias[m])                           (V proj, BIASM)
//     3: Cf = x + acc + bias[n], unpermuted scatter       (final)
//     4: Ch = rn(acc + bias[n])                           (QK proj)
//     5: Ch = rn(acc)                                     (scores -> S fp16)
template <int MODE, bool TRI, bool CAUSALK, int EPI, bool BIASM>
__global__ __launch_bounds__(256, MODE == 0 ? 2 : 1) void mma_fp16_kernel(
    const __half* __restrict__ A0, const __half* __restrict__ A1,
    const __half* __restrict__ B0, const __half* __restrict__ B1,
    float* __restrict__ Cf, __half* __restrict__ Ch, __half* __restrict__ Ch2,
    const float* __restrict__ bias, const float* __restrict__ xres,
    float alpha,
    int lda, int ldb, int ldc, int Kfull,
    long long strA, long long strB, long long strC)
{
    int nt = blockIdx.x, bz = blockIdx.z;
    int mt, seg = 0;
    if (TRI) {
        mt = blockIdx.y;
        if (nt > mt) return;
    } else if (CAUSALK) {
        int yy = blockIdx.y;          // 0..63
        mt = 31 - (yy >> 1);          // longest first
        seg = yy & 1;
    } else {
        mt = blockIdx.y;
    }
    int Ktile = CAUSALK ? (mt + 1) * 64 : Kfull;
    long long ksegoff = CAUSALK ? (long long)seg * Ktile : 0;

    extern __shared__ uint32_t smw[];
    uint32_t sbase = smem_u32(smw);

    int tid = threadIdx.x;
    int lane = tid & 31, wid = tid >> 5;
    int wm = (wid >> 2) * 64, wn = (wid & 3) * 32;
    int gid = lane >> 2, tg = lane & 3;
    int l8 = lane & 7, quad = lane >> 3;

    const __half* a0 = A0 + (long long)bz * strA + (long long)mt * 128 * lda + ksegoff;
    const __half* b0 = B0 + (long long)bz * strB + (long long)nt * 128 * ldb + ksegoff;
    const __half* a1 = (MODE == 2) ? A1 + (long long)bz * strA + (long long)mt * 128 * lda : nullptr;
    const __half* b1 = (MODE == 2) ? B1 + (long long)bz * strB + (long long)nt * 128 * ldb : nullptr;

    float acc[4][4][4];
    #pragma unroll
    for (int mi = 0; mi < 4; mi++)
        #pragma unroll
        for (int ni = 0; ni < 4; ni++)
            #pragma unroll
            for (int e = 0; e < 4; e++) acc[mi][ni][e] = 0.f;

    // tiles: 128 rows x 64 halves (128B rows), XOR swizzle within row = 16 KB
    const uint32_t TB = 16384u;
    const uint32_t NT_ = (MODE == 2) ? 4u : 2u;
    const uint32_t BUF = NT_ * TB;
    const uint32_t BOFF = (MODE == 2) ? 2u * TB : TB;

    const int NC = Ktile >> 6;   // k-chunk 64

    auto load_tile = [&](uint32_t dstbase, const __half* src, int ld, int koff) {
        #pragma unroll
        for (int j = 0; j < 4; j++) {
            int v = tid + j * 256;
            int row = v >> 3, c16 = v & 7;
            uint32_t dst = dstbase + (uint32_t)row * 128u
                         + (((uint32_t)c16 * 16u) ^ ((uint32_t)(row & 7) << 4));
            cpa16(dst, src + (long long)row * ld + koff + c16 * 8);
        }
    };
    auto load_chunk = [&](int p, int koff) {
        uint32_t pb = sbase + (uint32_t)p * BUF;
        load_tile(pb, a0, lda, koff);
        load_tile(pb + BOFF, b0, ldb, koff);
        if (MODE == 2) {
            load_tile(pb + TB, a1, lda, koff);
            load_tile(pb + 3u * TB, b1, ldb, koff);
        }
    };

    // 3-stage prologue (commits unconditional to keep group positions fixed)
    load_chunk(0, 0);
    cpa_commit();
    if (NC > 1) load_chunk(1, 64);
    cpa_commit();
    if (NC > 2) load_chunk(2, 128);
    cpa_commit();

    uint32_t a_row = (uint32_t)(wm + (quad & 1) * 8 + l8) * 128u;
    uint32_t a_cq  = (uint32_t)(quad >> 1) * 16u;
    uint32_t b_cq  = (uint32_t)(quad & 1) * 16u;
    uint32_t swl   = (uint32_t)l8 << 4;
    uint32_t b_row0 = (uint32_t)(wn + (0 + (quad >> 1)) * 8 + l8) * 128u;
    uint32_t b_row1 = (uint32_t)(wn + (2 + (quad >> 1)) * 8 + l8) * 128u;

    for (int c = 0; c < NC; c++) {
        cpa_wait2();
        __syncthreads();
        uint32_t Ab = sbase + (uint32_t)(c % 3) * BUF;
        uint32_t Bb = Ab + BOFF;

        #pragma unroll
        for (int kb = 0; kb < 4; kb++) {
            uint32_t acol = ((uint32_t)kb * 32u + a_cq) ^ swl;
            uint32_t bcol = ((uint32_t)kb * 32u + b_cq) ^ swl;
            uint32_t af[4][4], bf[2][4];
            #pragma unroll
            for (int mi = 0; mi < 4; mi++) {
                ldm_x4(af[mi], Ab + a_row + (uint32_t)mi * 2048u + acol);
                if (MODE == 2) {
                    uint32_t a1f[4];
                    ldm_x4(a1f, Ab + TB + a_row + (uint32_t)mi * 2048u + acol);
                    #pragma unroll
                    for (int j = 0; j < 4; j++)
                        af[mi][j] = hadd2_u32(af[mi][j], a1f[j]);
                }
            }
            ldm_x4(bf[0], Bb + b_row0 + bcol);
            ldm_x4(bf[1], Bb + b_row1 + bcol);

            #pragma unroll
            for (int ni = 0; ni < 4; ni++) {
                const uint32_t* bp = &bf[ni >> 1][(ni & 1) * 2];
                #pragma unroll
                for (int mi = 0; mi < 4; mi++)
                    mma16(acc[mi][ni], af[mi], bp);
            }
            if (MODE == 2) {
                uint32_t bfl[2][4];
                ldm_x4(bfl[0], Bb + TB + b_row0 + bcol);
                ldm_x4(bfl[1], Bb + TB + b_row1 + bcol);
                #pragma unroll
                for (int ni = 0; ni < 4; ni++) {
                    const uint32_t* bpl = &bfl[ni >> 1][(ni & 1) * 2];
                    #pragma unroll
                    for (int mi = 0; mi < 4; mi++)
                        mma16(acc[mi][ni], af[mi], bpl);
                }
            }
        }
        __syncthreads();
        if (c + 3 < NC) load_chunk((c + 3) % 3, (c + 3) * 64);
        cpa_commit();
    }

    // ---------------- epilogue ----------------
    #pragma unroll
    for (int mi = 0; mi < 4; mi++) {
        int r = wm + mi * 16 + gid;
        #pragma unroll
        for (int ni = 0; ni < 4; ni++) {
            int col = wn + ni * 8 + tg * 2;
            #pragma unroll
            for (int half_ = 0; half_ < 2; half_++) {
                int rr = r + half_ * 8;
                float v0 = acc[mi][ni][half_ * 2 + 0];
                float v1 = acc[mi][ni][half_ * 2 + 1];
                if (EPI == 1) {
                    __half* tgt = seg ? Ch2 : Ch;
                    long long off = (long long)bz * strC
                                  + (long long)(mt * 128 + rr) * ldc + nt * 128 + col;
                    *(__half2*)(tgt + off) = __floats2half2_rn(v0, v1);
                } else if (EPI == 2) {
                    float bv = BIASM ? bias[mt * 128 + rr] : 0.f;
                    __half* Cp = Ch + (long long)bz * strC
                               + (long long)(mt * 128 + rr) * ldc + nt * 128 + col;
                    *(__half2*)Cp = __floats2half2_rn(v0 + bv, v1 + bv);
                } else if (EPI == 3) {
                    int m = mt * 128 + rr;
                    int bidx = m >> 12, t = m & 4095;
                    int sidx = ((t & 63) << 6) | (t >> 6);
                    long long i0 = ((long long)bidx << 20)
                                 + ((long long)(nt * 128 + col) << 12) + sidx;
                    long long i1 = i0 + 4096;
                    Cf[i0] = xres[i0] + v0 + bias[nt * 128 + col];
                    Cf[i1] = xres[i1] + v1 + bias[nt * 128 + col + 1];
                } else if (EPI == 4) {
                    float b0v = bias[nt * 128 + col];
                    float b1v = bias[nt * 128 + col + 1];
                    __half* Cp = Ch + (long long)bz * strC
                               + (long long)(mt * 128 + rr) * ldc + nt * 128 + col;
                    *(__half2*)Cp = __floats2half2_rn(v0 + b0v, v1 + b1v);
                } else {  // EPI == 5
                    __half* Cp = Ch + (long long)bz * strC
                               + (long long)(mt * 128 + rr) * ldc + nt * 128 + col;
                    *(__half2*)Cp = __floats2half2_rn(v0, v1);
                }
            }
        }
    }
}

// ---------------- masked softmax: fp16 in/out, in place, half2 ---------------
__global__ __launch_bounds__(256) void softmax_kernel() {
    int row = blockIdx.x;
    int p = row & 4095;
    int wq = p >> 6;
    int L = (wq + 1) << 6;
    __half2* S2 = (__half2*)(g_s + (size_t)row * HWT);
    int L2 = L >> 1;
    int tid = threadIdx.x;
    __shared__ float red[8];
    const float NEG = -1e30f;

    float2 vals[8];
    float mx = NEG;
    #pragma unroll
    for (int it = 0; it < 8; it++) {
        int j = it * 256 + tid;
        float2 v = (j < L2) ? __half22float2(S2[j]) : make_float2(NEG, NEG);
        vals[it] = v;
        mx = fmaxf(mx, fmaxf(v.x, v.y));
    }
    #pragma unroll
    for (int o = 16; o > 0; o >>= 1)
        mx = fmaxf(mx, __shfl_xor_sync(0xffffffffu, mx, o));
    if ((tid & 31) == 0) red[tid >> 5] = mx;
    __syncthreads();
    mx = red[0];
    #pragma unroll
    for (int i = 1; i < 8; i++) mx = fmaxf(mx, red[i]);
    __syncthreads();

    float sum = 0.f;
    #pragma unroll
    for (int it = 0; it < 8; it++) {
        float e0 = __expf(vals[it].x - mx);
        float e1 = __expf(vals[it].y - mx);
        vals[it] = make_float2(e0, e1);
        sum += e0 + e1;
    }
    #pragma unroll
    for (int o = 16; o > 0; o >>= 1)
        sum += __shfl_xor_sync(0xffffffffu, sum, o);
    if ((tid & 31) == 0) red[tid >> 5] = sum;
    __syncthreads();
    sum = 0.f;
    #pragma unroll
    for (int i = 0; i < 8; i++) sum += red[i];

    float inv = 1.f / sum;
    #pragma unroll
    for (int it = 0; it < 8; it++) {
        int j = it * 256 + tid;
        if (j < L2)
            S2[j] = __floats2half2_rn(vals[it].x * inv, vals[it].y * inv);
    }
    if (!(wq & 1) && tid < 32)
        S2[L2 + tid] = __floats2half2_rn(0.f, 0.f);
}

// ---------------- launch ------------------------------------------------------
extern "C" void kernel_launch(void* const* d_in, const int* in_sizes, int n_in,
                              void* d_out, int out_size) {
    (void)in_sizes; (void)n_in; (void)out_size;
    const float* x   = (const float*)d_in[0];
    const float* gnw = (const float*)d_in[1];
    const float* gnb = (const float*)d_in[2];
    const float* w0  = (const float*)d_in[3];
    const float* b0  = (const float*)d_in[4];
    const float* w1  = (const float*)d_in[5];
    const float* b1  = (const float*)d_in[6];
    const float* w2  = (const float*)d_in[7];
    const float* b2  = (const float*)d_in[8];
    const float* w3  = (const float*)d_in[9];
    const float* b3  = (const float*)d_in[10];
    float* out = (float*)d_out;

    const int SM_M0 = 98304;    // 2 tiles x 16KB x 3 buffers
    const int SM_M2 = 196608;   // 4 tiles x 16KB x 3 buffers
    cudaFuncSetAttribute(mma_fp16_kernel<0, false, false, 4, false>,
                         cudaFuncAttributeMaxDynamicSharedMemorySize, SM_M0);
    cudaFuncSetAttribute(mma_fp16_kernel<0, false, false, 2, true>,
                         cudaFuncAttributeMaxDynamicSharedMemorySize, SM_M0);
    cudaFuncSetAttribute(mma_fp16_kernel<0, true, false, 5, false>,
                         cudaFuncAttributeMaxDynamicSharedMemorySize, SM_M0);
    cudaFuncSetAttribute(mma_fp16_kernel<0, false, true, 1, false>,
                         cudaFuncAttributeMaxDynamicSharedMemorySize, SM_M0);
    cudaFuncSetAttribute(mma_fp16_kernel<2, false, false, 3, false>,
                         cudaFuncAttributeMaxDynamicSharedMemorySize, SM_M2);

    void *p0, *p1, *p2, *p3, *p4, *p5, *p6, *p7, *p8, *p9;
    cudaGetSymbolAddress(&p0, g_hn);
    cudaGetSymbolAddress(&p1, g_qk);
    cudaGetSymbolAddress(&p2, g_vt);
    cudaGetSymbolAddress(&p3, g_h_p0);
    cudaGetSymbolAddress(&p4, g_h_p1);
    cudaGetSymbolAddress(&p5, g_wqk);
    cudaGetSymbolAddress(&p6, g_w2t);
    cudaGetSymbolAddress(&p7, g_w3hi);
    cudaGetSymbolAddress(&p8, g_w3lo);
    cudaGetSymbolAddress(&p9, g_s);
    __half* hn  = (__half*)p0;
    __half* qk  = (__half*)p1;
    __half* vt  = (__half*)p2;
    __half* hp0 = (__half*)p3;  __half* hp1 = (__half*)p4;
    __half* wqk = (__half*)p5;
    __half* w2t = (__half*)p6;
    __half* w3h = (__half*)p7;  __half* w3l = (__half*)p8;
    __half* s   = (__half*)p9;

    void* pb;
    cudaGetSymbolAddress(&pb, g_bqk);
    float* bqk = (float*)pb;

    const long long HN_STR = (long long)HWT * CCH;       // 1,048,576
    const long long QK_STR = (long long)HWT * 2 * CCH;   // 2,097,152
    const long long S_STR  = (long long)HWT * HWT;       // 16,777,216

    // 1. GroupNorm (permuted, fp16)
    groupnorm_kernel<<<512, 256>>>(x, gnw, gnb);

    // 2. weight prep
    wprep_all<<<256, dim3(32, 32)>>>(w0, b0, w1, b1, w2, w3);

    // 3. Fused Q|K projection -> g_qk [tok][512]
    dim3 gqk(4, 128, 1);
    mma_fp16_kernel<0, false, false, 4, false><<<gqk, 256, SM_M0>>>(
        hn, nullptr, wqk, nullptr, nullptr, qk, nullptr, bqk, nullptr,
        1.0f, CCH, CCH, 2 * CCH, CCH, 0, 0, 0);

    // 4. V projection, transposed out: vt[c][p] = W2^T x HN^T + b2
    dim3 gv(32, 2, 4);
    mma_fp16_kernel<0, false, false, 2, true><<<gv, 256, SM_M0>>>(
        w2t, nullptr, hn, nullptr, nullptr, vt, nullptr, b2, nullptr,
        1.0f, CCH, CCH, HWT, CCH, 0, HN_STR, HN_STR);

    // 5. Scores S = Q*K^T (triangular tiles, fp16 store)
    dim3 gs(32, 32, 4);
    mma_fp16_kernel<0, true, false, 5, false><<<gs, 256, SM_M0>>>(
        qk, nullptr, qk + CCH, nullptr, nullptr, s, nullptr, nullptr, nullptr,
        1.0f, 2 * CCH, 2 * CCH, HWT, CCH, QK_STR, QK_STR, S_STR);

    // 6. Softmax (fp16 in/out, in place)
    softmax_kernel<<<NTOK, 256>>>();

    // 7. H = P * V^T, K split into 2 segments -> fp16 partials hp0/hp1
    dim3 gp(2, 64, 4);
    mma_fp16_kernel<0, false, true, 1, false><<<gp, 256, SM_M0>>>(
        s, nullptr, vt, nullptr, nullptr, hp0, hp1, nullptr, nullptr,
        1.0f, HWT, HWT, CCH, 0, S_STR, HN_STR, HN_STR);

    // 8. out = x + (hp0+hp1)*(w3hi+w3lo) + b3 (2-mma, scatter + unpermute)
    dim3 gf(2, 128, 1);
    mma_fp16_kernel<2, false, false, 3, false><<<gf, 256, SM_M2>>>(
        hp0, hp1, w3h, w3l, out, nullptr, nullptr, b3, x,
        1.0f, CCH, CCH, 0, CCH, 0, 0, 0);
}

// round 14
// speedup vs baseline: 3.9558x; 1.0705x over previous
#include <cuda_runtime.h>
#include <cuda_fp16.h>
#include <math.h>
#include <stdint.h>

// Problem dims
#define BCH 4
#define CCH 256
#define HWT 4096          // H*W = 64*64
#define NTOK 16384        // B*HW

#define QK_STRC ((long long)HWT * 2 * CCH)
#define S_STRC  ((long long)HWT * HWT)

// Token order inside each batch is PERMUTED: p = w*64 + h. Causal mask becomes
// block-lower-triangular at 64-token granularity, diagonal fully allowed.

// ---------------- scratch ------------------------------------------------------
__device__ __align__(256) __half g_hn  [(size_t)NTOK * CCH];         // fp16
__device__ __align__(256) __half g_qk  [(size_t)NTOK * 2 * CCH];     // [tok][512]: Q|K
__device__ __align__(256) __half g_vt  [(size_t)NTOK * CCH];         // [b][c][p]
__device__ __align__(256) __half g_h_p0[(size_t)NTOK * CCH];         // PV K-partial 0
__device__ __align__(256) __half g_h_p1[(size_t)NTOK * CCH];         // PV K-partial 1
__device__ __align__(256) __half g_wqk [2 * CCH * CCH];              // [512][256] w0t/16 | w1t
__device__ __align__(256) __half g_w2t [CCH * CCH];
__device__ __align__(256) __half g_w3hi[CCH * CCH];
__device__ __align__(256) __half g_w3lo[CCH * CCH];
__device__ __align__(256) float  g_bqk [2 * CCH];                    // b0/16 | b1
__device__ __align__(256) __half g_s   [(size_t)BCH * HWT * HWT];    // S then P (in place)

// ---------------- helpers -----------------------------------------------------
__device__ __forceinline__ uint32_t smem_u32(const void* p) {
    uint32_t a;
    asm("{ .reg .u64 t; cvta.to.shared.u64 t, %1; cvt.u32.u64 %0, t; }"
        : "=r"(a) : "l"(p));
    return a;
}
__device__ __forceinline__ void cpa16(uint32_t dst, const void* src) {
    asm volatile("cp.async.cg.shared.global [%0], [%1], 16;"
                 :: "r"(dst), "l"(src));
}
__device__ __forceinline__ void cpa_commit() {
    asm volatile("cp.async.commit_group;" ::: "memory");
}
__device__ __forceinline__ void cpa_wait1() {
    asm volatile("cp.async.wait_group 1;" ::: "memory");
}
__device__ __forceinline__ void mma16(float* c, const uint32_t* a, const uint32_t* b) {
    asm volatile("mma.sync.aligned.m16n8k16.row.col.f32.f16.f16.f32 "
        "{%0,%1,%2,%3}, {%4,%5,%6,%7}, {%8,%9}, {%0,%1,%2,%3};"
        : "+f"(c[0]), "+f"(c[1]), "+f"(c[2]), "+f"(c[3])
        : "r"(a[0]), "r"(a[1]), "r"(a[2]), "r"(a[3]), "r"(b[0]), "r"(b[1]));
}
__device__ __forceinline__ void ldm_x4(uint32_t* r, uint32_t addr) {
    asm volatile("ldmatrix.sync.aligned.m8n8.x4.shared.b16 {%0,%1,%2,%3}, [%4];"
        : "=r"(r[0]), "=r"(r[1]), "=r"(r[2]), "=r"(r[3]) : "r"(addr));
}
__device__ __forceinline__ uint32_t hadd2_u32(uint32_t a, uint32_t b) {
    __half2 r = __hadd2(*(__half2*)&a, *(__half2*)&b);
    return *(uint32_t*)&r;
}

// ---------------- GroupNorm -> permuted hn (fp16) -----------------------------
__global__ __launch_bounds__(256) void groupnorm_kernel(
    const float* __restrict__ x,
    const float* __restrict__ gnw,
    const float* __restrict__ gnb)
{
    __shared__ float tile[CCH][33];
    __shared__ float sw[CCH];
    __shared__ float sb[CCH];
    int tid = threadIdx.x;
    int b = blockIdx.x >> 7;
    int hwbase = (blockIdx.x & 127) << 5;
    int tx = tid & 31, ty = tid >> 5;

    const float* xb = x + (size_t)b * CCH * HWT;
    for (int c = ty; c < CCH; c += 8)
        tile[c][tx] = xb[(size_t)c * HWT + hwbase + tx];
    sw[tid] = gnw[tid];
    sb[tid] = gnb[tid];
    __syncthreads();

    int tok = tx;
    #pragma unroll
    for (int gi = 0; gi < 4; gi++) {
        int c0 = (ty + gi * 8) * 8;
        float s = 0.f, ss = 0.f;
        #pragma unroll
        for (int j = 0; j < 8; j++) {
            float v = tile[c0 + j][tok];
            s += v; ss += v * v;
        }
        float m   = s * 0.125f;
        float var = ss * 0.125f - m * m;
        float r   = rsqrtf(var + 1e-6f);
        #pragma unroll
        for (int j = 0; j < 8; j++) {
            int c = c0 + j;
            tile[c][tok] = (tile[c][tok] - m) * r * sw[c] + sb[c];
        }
    }
    __syncthreads();

    int h = hwbase >> 6;
    __half* hh = g_hn + ((size_t)b << 12) * CCH;
    for (int it = 0; it < 32; it++) {
        int w = (hwbase + it) & 63;
        int p = (w << 6) | h;
        hh[(size_t)p * CCH + tid] = __float2half_rn(tile[tid][it]);
    }
}

// ---------------- weight prep -------------------------------------------------
__global__ void wprep_all(const float* __restrict__ w0, const float* __restrict__ b0,
                          const float* __restrict__ w1, const float* __restrict__ b1,
                          const float* __restrict__ w2, const float* __restrict__ w3)
{
    __shared__ float t[32][33];
    int bid = blockIdx.x;
    int mat = bid >> 6;
    int tile_ = bid & 63;
    int bx = (tile_ & 7) * 32, by = (tile_ >> 3) * 32;
    int tx = threadIdx.x, ty = threadIdx.y;

    const float* w = (mat == 0) ? w0 : (mat == 1) ? w1 : (mat == 2) ? w2 : w3;
    t[ty][tx] = w[(by + ty) * CCH + bx + tx];
    __syncthreads();
    float v = t[tx][ty];
    int dst = (bx + ty) * CCH + by + tx;
    if (mat == 0) {
        g_wqk[dst] = __float2half_rn(v * 0.0625f);
    } else if (mat == 1) {
        g_wqk[CCH * CCH + dst] = __float2half_rn(v);
    } else if (mat == 2) {
        g_w2t[dst] = __float2half_rn(v);
    } else {
        __half hi = __float2half_rn(v);
        g_w3hi[dst] = hi;
        g_w3lo[dst] = __float2half_rn(v - __half2float(hi));
    }
    if (bid == 0) {
        int t0 = ty * 32 + tx;
        if (t0 < 256)      g_bqk[t0] = b0[t0] * 0.0625f;
        else if (t0 < 512) g_bqk[t0] = b1[t0 - 256];
    }
}

// ---------------- scores: A-resident 128x256 tile, 2-stage B stream -----------
// Q tile (128 x 256) loaded once; two 128-col K halves streamed. Causal skip.
__global__ __launch_bounds__(256, 2) void scores_kernel() {
    int nt2 = blockIdx.x;            // 0..15
    int mt  = blockIdx.y;            // 0..31
    int bz  = blockIdx.z;
    if (2 * nt2 > mt) return;
    int nHalves = (2 * nt2 + 1 <= mt) ? 2 : 1;

    extern __shared__ uint32_t smw[];
    uint32_t sbase = smem_u32(smw);
    uint32_t Abase = sbase;               // 4 chunks x 16KB (resident)
    uint32_t Bbase = sbase + 65536u;      // 2 buf x 16KB

    int tid = threadIdx.x;
    int lane = tid & 31, wid = tid >> 5;
    int wm = (wid >> 2) * 64, wn = (wid & 3) * 32;
    int gid = lane >> 2, tg = lane & 3;
    int l8 = lane & 7, quad = lane >> 3;

    const __half* Ap = g_qk + (long long)bz * QK_STRC + (long long)(mt * 128) * 512;
    const __half* Bp = g_qk + 256 + (long long)bz * QK_STRC + (long long)(nt2 * 256) * 512;
    __half* Sp = g_s + (long long)bz * S_STRC + (long long)(mt * 128) * HWT + nt2 * 256;

    auto load_tile = [&](uint32_t dstbase, const __half* src, int koff) {
        #pragma unroll
        for (int j = 0; j < 4; j++) {
            int v = tid + j * 256;
            int row = v >> 3, c16 = v & 7;
            uint32_t dst = dstbase + (uint32_t)row * 128u
                         + (((uint32_t)c16 * 16u) ^ ((uint32_t)(row & 7) << 4));
            cpa16(dst, src + (long long)row * 512 + koff + c16 * 8);
        }
    };

    // prologue: A (all 4 chunks) + B chunk g0 -> group0; B chunk g1 -> group1
    #pragma unroll
    for (int c = 0; c < 4; c++) load_tile(Abase + (uint32_t)c * 16384u, Ap, c * 64);
    load_tile(Bbase, Bp, 0);
    cpa_commit();
    load_tile(Bbase + 16384u, Bp, 64);
    cpa_commit();

    uint32_t a_row = (uint32_t)(wm + (quad & 1) * 8 + l8) * 128u;
    uint32_t a_cq  = (uint32_t)(quad >> 1) * 16u;
    uint32_t b_cq  = (uint32_t)(quad & 1) * 16u;
    uint32_t swl   = (uint32_t)l8 << 4;
    uint32_t b_row0 = (uint32_t)(wn + (quad >> 1) * 8 + l8) * 128u;
    uint32_t b_row1 = (uint32_t)(wn + (2 + (quad >> 1)) * 8 + l8) * 128u;

    for (int h = 0; h < nHalves; h++) {
        float acc[4][4][4];
        #pragma unroll
        for (int mi = 0; mi < 4; mi++)
            #pragma unroll
            for (int ni = 0; ni < 4; ni++)
                #pragma unroll
                for (int e = 0; e < 4; e++) acc[mi][ni][e] = 0.f;

        for (int c = 0; c < 4; c++) {
            cpa_wait1();
            __syncthreads();
            int g = h * 4 + c;
            uint32_t Ab = Abase + (uint32_t)c * 16384u;
            uint32_t Bb = Bbase + (uint32_t)(g & 1) * 16384u;

            #pragma unroll
            for (int kb = 0; kb < 4; kb++) {
                uint32_t acol = ((uint32_t)kb * 32u + a_cq) ^ swl;
                uint32_t bcol = ((uint32_t)kb * 32u + b_cq) ^ swl;
                uint32_t af[4][4], bf[2][4];
                #pragma unroll
                for (int mi = 0; mi < 4; mi++)
                    ldm_x4(af[mi], Ab + a_row + (uint32_t)mi * 2048u + acol);
                ldm_x4(bf[0], Bb + b_row0 + bcol);
                ldm_x4(bf[1], Bb + b_row1 + bcol);
                #pragma unroll
                for (int ni = 0; ni < 4; ni++) {
                    const uint32_t* bp = &bf[ni >> 1][(ni & 1) * 2];
                    #pragma unroll
                    for (int mi = 0; mi < 4; mi++)
                        mma16(acc[mi][ni], af[mi], bp);
                }
            }
            __syncthreads();
            int gn = g + 2;
            if (gn < nHalves * 4) {
                const __half* Bsrc = Bp + (long long)((gn >= 4) ? 128 : 0) * 512;
                load_tile(Bbase + (uint32_t)(gn & 1) * 16384u, Bsrc, (gn & 3) * 64);
            }
            cpa_commit();
        }

        // store S half (fp16)
        __half* Cp = Sp + h * 128;
        #pragma unroll
        for (int mi = 0; mi < 4; mi++) {
            int r = wm + mi * 16 + gid;
            #pragma unroll
            for (int ni = 0; ni < 4; ni++) {
                int col = wn + ni * 8 + tg * 2;
                #pragma unroll
                for (int half_ = 0; half_ < 2; half_++) {
                    int rr = r + half_ * 8;
                    *(__half2*)(Cp + (long long)rr * HWT + col) =
                        __floats2half2_rn(acc[mi][ni][half_ * 2 + 0],
                                          acc[mi][ni][half_ * 2 + 1]);
                }
            }
        }
    }
}

// ---------------- unified fp16 tensor-core NT GEMM (2-stage, ldmatrix) --------
// MODE 0: single (A,B). MODE 2: A = A0+A1 (hadd2), B = B0,B1 (2 mmas).
// CAUSALK: PV K-split (y -> mt desc, seg 0/1, Ktile=(mt+1)*64 per seg).
// EPI 1: partial fp16 store -> (seg? Ch2 : Ch)           (PV)
//     2: Ch = rn(acc + bias[m])                           (V proj, BIASM)
//     3: Cf = x + acc + bias[n], unpermuted scatter       (final)
//     4: Ch = rn(acc + bias[n])                           (QK proj)
template <int MODE, bool CAUSALK, int EPI, bool BIASM>
__global__ __launch_bounds__(256, MODE == 0 ? 2 : 1) void mma_fp16_kernel(
    const __half* __restrict__ A0, const __half* __restrict__ A1,
    const __half* __restrict__ B0, const __half* __restrict__ B1,
    float* __restrict__ Cf, __half* __restrict__ Ch, __half* __restrict__ Ch2,
    const float* __restrict__ bias, const float* __restrict__ xres,
    int lda, int ldb, int ldc, int Kfull,
    long long strA, long long strB, long long strC)
{
    int nt = blockIdx.x, bz = blockIdx.z;
    int mt, seg = 0;
    if (CAUSALK) {
        int yy = blockIdx.y;          // 0..63
        mt = 31 - (yy >> 1);          // longest first
        seg = yy & 1;
    } else {
        mt = blockIdx.y;
    }
    int Ktile = CAUSALK ? (mt + 1) * 64 : Kfull;
    long long ksegoff = CAUSALK ? (long long)seg * Ktile : 0;

    extern __shared__ uint32_t smw[];
    uint32_t sbase = smem_u32(smw);

    int tid = threadIdx.x;
    int lane = tid & 31, wid = tid >> 5;
    int wm = (wid >> 2) * 64, wn = (wid & 3) * 32;
    int gid = lane >> 2, tg = lane & 3;
    int l8 = lane & 7, quad = lane >> 3;

    const __half* a0 = A0 + (long long)bz * strA + (long long)mt * 128 * lda + ksegoff;
    const __half* b0 = B0 + (long long)bz * strB + (long long)nt * 128 * ldb + ksegoff;
    const __half* a1 = (MODE == 2) ? A1 + (long long)bz * strA + (long long)mt * 128 * lda : nullptr;
    const __half* b1 = (MODE == 2) ? B1 + (long long)bz * strB + (long long)nt * 128 * ldb : nullptr;

    float acc[4][4][4];
    #pragma unroll
    for (int mi = 0; mi < 4; mi++)
        #pragma unroll
        for (int ni = 0; ni < 4; ni++)
            #pragma unroll
            for (int e = 0; e < 4; e++) acc[mi][ni][e] = 0.f;

    const uint32_t TB = 16384u;
    const uint32_t NT_ = (MODE == 2) ? 4u : 2u;
    const uint32_t BUF = NT_ * TB;
    const uint32_t BOFF = (MODE == 2) ? 2u * TB : TB;

    const int NC = Ktile >> 6;   // k-chunk 64

    auto load_tile = [&](uint32_t dstbase, const __half* src, int ld, int koff) {
        #pragma unroll
        for (int j = 0; j < 4; j++) {
            int v = tid + j * 256;
            int row = v >> 3, c16 = v & 7;
            uint32_t dst = dstbase + (uint32_t)row * 128u
                         + (((uint32_t)c16 * 16u) ^ ((uint32_t)(row & 7) << 4));
            cpa16(dst, src + (long long)row * ld + koff + c16 * 8);
        }
    };
    auto load_chunk = [&](int p, int koff) {
        uint32_t pb = sbase + (uint32_t)p * BUF;
        load_tile(pb, a0, lda, koff);
        load_tile(pb + BOFF, b0, ldb, koff);
        if (MODE == 2) {
            load_tile(pb + TB, a1, lda, koff);
            load_tile(pb + 3u * TB, b1, ldb, koff);
        }
    };

    load_chunk(0, 0);
    cpa_commit();
    if (NC > 1) load_chunk(1, 64);
    cpa_commit();

    uint32_t a_row = (uint32_t)(wm + (quad & 1) * 8 + l8) * 128u;
    uint32_t a_cq  = (uint32_t)(quad >> 1) * 16u;
    uint32_t b_cq  = (uint32_t)(quad & 1) * 16u;
    uint32_t swl   = (uint32_t)l8 << 4;
    uint32_t b_row0 = (uint32_t)(wn + (quad >> 1) * 8 + l8) * 128u;
    uint32_t b_row1 = (uint32_t)(wn + (2 + (quad >> 1)) * 8 + l8) * 128u;

    for (int c = 0; c < NC; c++) {
        cpa_wait1();
        __syncthreads();
        int p = c & 1;
        uint32_t Ab = sbase + (uint32_t)p * BUF;
        uint32_t Bb = Ab + BOFF;

        #pragma unroll
        for (int kb = 0; kb < 4; kb++) {
            uint32_t acol = ((uint32_t)kb * 32u + a_cq) ^ swl;
            uint32_t bcol = ((uint32_t)kb * 32u + b_cq) ^ swl;
            uint32_t af[4][4], bf[2][4];
            #pragma unroll
            for (int mi = 0; mi < 4; mi++) {
                ldm_x4(af[mi], Ab + a_row + (uint32_t)mi * 2048u + acol);
                if (MODE == 2) {
                    uint32_t a1f[4];
                    ldm_x4(a1f, Ab + TB + a_row + (uint32_t)mi * 2048u + acol);
                    #pragma unroll
                    for (int j = 0; j < 4; j++)
                        af[mi][j] = hadd2_u32(af[mi][j], a1f[j]);
                }
            }
            ldm_x4(bf[0], Bb + b_row0 + bcol);
            ldm_x4(bf[1], Bb + b_row1 + bcol);

            #pragma unroll
            for (int ni = 0; ni < 4; ni++) {
                const uint32_t* bp = &bf[ni >> 1][(ni & 1) * 2];
                #pragma unroll
                for (int mi = 0; mi < 4; mi++)
                    mma16(acc[mi][ni], af[mi], bp);
            }
            if (MODE == 2) {
                uint32_t bfl[2][4];
                ldm_x4(bfl[0], Bb + TB + b_row0 + bcol);
                ldm_x4(bfl[1], Bb + TB + b_row1 + bcol);
                #pragma unroll
                for (int ni = 0; ni < 4; ni++) {
                    const uint32_t* bpl = &bfl[ni >> 1][(ni & 1) * 2];
                    #pragma unroll
                    for (int mi = 0; mi < 4; mi++)
                        mma16(acc[mi][ni], af[mi], bpl);
                }
            }
        }
        __syncthreads();
        if (c + 2 < NC) load_chunk(p, (c + 2) * 64);
        cpa_commit();
    }

    // ---------------- epilogue ----------------
    #pragma unroll
    for (int mi = 0; mi < 4; mi++) {
        int r = wm + mi * 16 + gid;
        #pragma unroll
        for (int ni = 0; ni < 4; ni++) {
            int col = wn + ni * 8 + tg * 2;
            #pragma unroll
            for (int half_ = 0; half_ < 2; half_++) {
                int rr = r + half_ * 8;
                float v0 = acc[mi][ni][half_ * 2 + 0];
                float v1 = acc[mi][ni][half_ * 2 + 1];
                if (EPI == 1) {
                    __half* tgt = seg ? Ch2 : Ch;
                    long long off = (long long)bz * strC
                                  + (long long)(mt * 128 + rr) * ldc + nt * 128 + col;
                    *(__half2*)(tgt + off) = __floats2half2_rn(v0, v1);
                } else if (EPI == 2) {
                    float bv = BIASM ? bias[mt * 128 + rr] : 0.f;
                    __half* Cp = Ch + (long long)bz * strC
                               + (long long)(mt * 128 + rr) * ldc + nt * 128 + col;
                    *(__half2*)Cp = __floats2half2_rn(v0 + bv, v1 + bv);
                } else if (EPI == 3) {
                    int m = mt * 128 + rr;
                    int bidx = m >> 12, t = m & 4095;
                    int sidx = ((t & 63) << 6) | (t >> 6);
                    long long i0 = ((long long)bidx << 20)
                                 + ((long long)(nt * 128 + col) << 12) + sidx;
                    long long i1 = i0 + 4096;
                    Cf[i0] = xres[i0] + v0 + bias[nt * 128 + col];
                    Cf[i1] = xres[i1] + v1 + bias[nt * 128 + col + 1];
                } else {  // EPI == 4
                    float b0v = bias[nt * 128 + col];
                    float b1v = bias[nt * 128 + col + 1];
                    __half* Cp = Ch + (long long)bz * strC
                               + (long long)(mt * 128 + rr) * ldc + nt * 128 + col;
                    *(__half2*)Cp = __floats2half2_rn(v0 + b0v, v1 + b1v);
                }
            }
        }
    }
}

// ---------------- masked softmax: fp16 in/out, in place, half2 ---------------
__global__ __launch_bounds__(256) void softmax_kernel() {
    int row = blockIdx.x;
    int p = row & 4095;
    int wq = p >> 6;
    int L = (wq + 1) << 6;
    __half2* S2 = (__half2*)(g_s + (size_t)row * HWT);
    int L2 = L >> 1;
    int tid = threadIdx.x;
    __shared__ float red[8];
    const float NEG = -1e30f;

    float2 vals[8];
    float mx = NEG;
    #pragma unroll
    for (int it = 0; it < 8; it++) {
        int j = it * 256 + tid;
        float2 v = (j < L2) ? __half22float2(S2[j]) : make_float2(NEG, NEG);
        vals[it] = v;
        mx = fmaxf(mx, fmaxf(v.x, v.y));
    }
    #pragma unroll
    for (int o = 16; o > 0; o >>= 1)
        mx = fmaxf(mx, __shfl_xor_sync(0xffffffffu, mx, o));
    if ((tid & 31) == 0) red[tid >> 5] = mx;
    __syncthreads();
    mx = red[0];
    #pragma unroll
    for (int i = 1; i < 8; i++) mx = fmaxf(mx, red[i]);
    __syncthreads();

    float sum = 0.f;
    #pragma unroll
    for (int it = 0; it < 8; it++) {
        float e0 = __expf(vals[it].x - mx);
        float e1 = __expf(vals[it].y - mx);
        vals[it] = make_float2(e0, e1);
        sum += e0 + e1;
    }
    #pragma unroll
    for (int o = 16; o > 0; o >>= 1)
        sum += __shfl_xor_sync(0xffffffffu, sum, o);
    if ((tid & 31) == 0) red[tid >> 5] = sum;
    __syncthreads();
    sum = 0.f;
    #pragma unroll
    for (int i = 0; i < 8; i++) sum += red[i];

    float inv = 1.f / sum;
    #pragma unroll
    for (int it = 0; it < 8; it++) {
        int j = it * 256 + tid;
        if (j < L2)
            S2[j] = __floats2half2_rn(vals[it].x * inv, vals[it].y * inv);
    }
    if (!(wq & 1) && tid < 32)
        S2[L2 + tid] = __floats2half2_rn(0.f, 0.f);
}

// ---------------- launch ------------------------------------------------------
extern "C" void kernel_launch(void* const* d_in, const int* in_sizes, int n_in,
                              void* d_out, int out_size) {
    (void)in_sizes; (void)n_in; (void)out_size;
    const float* x   = (const float*)d_in[0];
    const float* gnw = (const float*)d_in[1];
    const float* gnb = (const float*)d_in[2];
    const float* w0  = (const float*)d_in[3];
    const float* b0  = (const float*)d_in[4];
    const float* w1  = (const float*)d_in[5];
    const float* b1  = (const float*)d_in[6];
    const float* w2  = (const float*)d_in[7];
    const float* b2  = (const float*)d_in[8];
    const float* w3  = (const float*)d_in[9];
    const float* b3  = (const float*)d_in[10];
    float* out = (float*)d_out;

    const int SM_M0  = 65536;    // 2 tiles x 16KB x 2 buffers
    const int SM_M2  = 131072;   // 4 tiles x 16KB x 2 buffers
    const int SM_SC  = 98304;    // A resident 64KB + B 2x16KB
    cudaFuncSetAttribute(mma_fp16_kernel<0, false, 4, false>,
                         cudaFuncAttributeMaxDynamicSharedMemorySize, SM_M0);
    cudaFuncSetAttribute(mma_fp16_kernel<0, false, 2, true>,
                         cudaFuncAttributeMaxDynamicSharedMemorySize, SM_M0);
    cudaFuncSetAttribute(mma_fp16_kernel<0, true, 1, false>,
                         cudaFuncAttributeMaxDynamicSharedMemorySize, SM_M0);
    cudaFuncSetAttribute(mma_fp16_kernel<2, false, 3, false>,
                         cudaFuncAttributeMaxDynamicSharedMemorySize, SM_M2);
    cudaFuncSetAttribute(scores_kernel,
                         cudaFuncAttributeMaxDynamicSharedMemorySize, SM_SC);

    void *p0, *p1, *p2, *p3, *p4, *p5, *p6, *p7, *p8, *p9;
    cudaGetSymbolAddress(&p0, g_hn);
    cudaGetSymbolAddress(&p1, g_qk);
    cudaGetSymbolAddress(&p2, g_vt);
    cudaGetSymbolAddress(&p3, g_h_p0);
    cudaGetSymbolAddress(&p4, g_h_p1);
    cudaGetSymbolAddress(&p5, g_wqk);
    cudaGetSymbolAddress(&p6, g_w2t);
    cudaGetSymbolAddress(&p7, g_w3hi);
    cudaGetSymbolAddress(&p8, g_w3lo);
    cudaGetSymbolAddress(&p9, g_s);
    __half* hn  = (__half*)p0;
    __half* qk  = (__half*)p1;
    __half* vt  = (__half*)p2;
    __half* hp0 = (__half*)p3;  __half* hp1 = (__half*)p4;
    __half* wqk = (__half*)p5;
    __half* w2t = (__half*)p6;
    __half* w3h = (__half*)p7;  __half* w3l = (__half*)p8;
    __half* s   = (__half*)p9;

    void* pb;
    cudaGetSymbolAddress(&pb, g_bqk);
    float* bqk = (float*)pb;

    const long long HN_STR = (long long)HWT * CCH;       // 1,048,576
    const long long S_STR  = (long long)HWT * HWT;       // 16,777,216

    // 1. GroupNorm (permuted, fp16)
    groupnorm_kernel<<<512, 256>>>(x, gnw, gnb);

    // 2. weight prep
    wprep_all<<<256, dim3(32, 32)>>>(w0, b0, w1, b1, w2, w3);

    // 3. Fused Q|K projection -> g_qk [tok][512]
    dim3 gqk(4, 128, 1);
    mma_fp16_kernel<0, false, 4, false><<<gqk, 256, SM_M0>>>(
        hn, nullptr, wqk, nullptr, nullptr, qk, nullptr, bqk, nullptr,
        CCH, CCH, 2 * CCH, CCH, 0, 0, 0);

    // 4. V projection, transposed out: vt[c][p] = W2^T x HN^T + b2
    dim3 gv(32, 2, 4);
    mma_fp16_kernel<0, false, 2, true><<<gv, 256, SM_M0>>>(
        w2t, nullptr, hn, nullptr, nullptr, vt, nullptr, b2, nullptr,
        CCH, CCH, HWT, CCH, 0, HN_STR, HN_STR);

    // 5. Scores S = Q*K^T (A-resident 128x256 tiles, causal skip, fp16 store)
    dim3 gsc(16, 32, 4);
    scores_kernel<<<gsc, 256, SM_SC>>>();

    // 6. Softmax (fp16 in/out, in place)
    softmax_kernel<<<NTOK, 256>>>();

    // 7. H = P * V^T, K split into 2 segments -> fp16 partials hp0/hp1
    dim3 gp(2, 64, 4);
    mma_fp16_kernel<0, true, 1, false><<<gp, 256, SM_M0>>>(
        s, nullptr, vt, nullptr, nullptr, hp0, hp1, nullptr, nullptr,
        HWT, HWT, CCH, 0, S_STR, HN_STR, HN_STR);

    // 8. out = x + (hp0+hp1)*(w3hi+w3lo) + b3 (2-mma, scatter + unpermute)
    dim3 gf(2, 128, 1);
    mma_fp16_kernel<2, false, 3, false><<<gf, 256, SM_M2>>>(
        hp0, hp1, w3h, w3l, out, nullptr, nullptr, b3, x,
        CCH, CCH, 0, CCH, 0, 0, 0);
}